// round 2
// baseline (speedup 1.0000x reference)
#include <cuda_runtime.h>

#define D   512
#define NSUP 512
#define NQMAX 16384
#define NITER 14

// ---------------- device scratch (no allocations allowed) ----------------
__device__ float g_mask[NSUP];     // 1.0 if label==0 else 0.0
__device__ float g_cnt[2];
__device__ float g_csum[2][D];
__device__ float g_mall[D];
__device__ float g_mean[2][D];
__device__ float g_G[D * D];
__device__ float g_G0[D * D];
__device__ float g_A[2 * D * D];
__device__ float g_NS0[2 * D * D];
__device__ float g_NS1[2 * D * D];
__device__ float g_T[2 * D * D];
__device__ float g_fro[2];
__device__ float g_w[2][D];
__device__ float g_b[2];
__device__ float g_S[2][NQMAX];

// ---------------- K0: build label mask, robust to int32 vs int64 storage ----------------
// Reads only the first 512 uint32 words for detection (safe under both layouts:
// int32 storage = 2048 B exactly; int64 storage = 4096 B). Labels are {0,1}, so
// under int64 (little-endian) every odd word is 0; under int32 the odd words are
// random 0/1 labels — P(all 256 zero) ~ 2^-256.
__global__ void k_mask(const unsigned int* __restrict__ labw) {
    __shared__ int oddOr;
    int i = threadIdx.x;  // 512 threads
    if (i == 0) oddOr = 0;
    __syncthreads();
    unsigned int w = labw[i];
    if ((i & 1) && w) atomicOr(&oddOr, 1);
    __syncthreads();
    unsigned int li = oddOr ? labw[i] : labw[2 * i];
    g_mask[i] = (li == 0) ? 1.f : 0.f;
}

// ---------------- K1: per-class sums + overall mean + counts ----------------
__global__ void k_sums(const float* __restrict__ X) {
    __shared__ float m[NSUP];
    int t = threadIdx.x;  // 128 threads
    for (int i = t; i < NSUP; i += 128) m[i] = g_mask[i];
    __syncthreads();
    int j = blockIdx.x * 128 + t;  // column
    float sa = 0.f, s0 = 0.f;
    for (int i = 0; i < NSUP; i++) {
        float x = X[i * D + j];
        sa += x;
        s0 += m[i] * x;
    }
    g_mall[j]    = sa / (float)NSUP;
    g_csum[0][j] = s0;
    g_csum[1][j] = sa - s0;
    if (blockIdx.x == 0 && t < 32) {
        float c0 = 0.f;
        for (int i = t; i < NSUP; i += 32) c0 += m[i];
        for (int o = 16; o > 0; o >>= 1) c0 += __shfl_down_sync(0xffffffffu, c0, o);
        if (t == 0) { g_cnt[0] = c0; g_cnt[1] = (float)NSUP - c0; }
    }
}

// ---------------- K2: class means (+ zero fro accumulators) ----------------
__global__ void k_means() {
    int c = blockIdx.x, j = threadIdx.x;
    g_mean[c][j] = g_csum[c][j] / g_cnt[c];
    if (j == 0) g_fro[c] = 0.f;
}

// ---------------- K3: Gram matrices G = X^T X and G0 = X^T diag(mask0) X ----------------
__global__ void k_gram(const float* __restrict__ X) {
    __shared__ float As[16][33], Bs[16][33], Ms[16];
    int tx = threadIdx.x, ty = threadIdx.y;
    int t = ty * 16 + tx;
    int i0 = blockIdx.x * 32, j0 = blockIdx.y * 32;
    float aA[2][2] = {}, a0[2][2] = {};
    int rr = t >> 4, cc = (t & 15) * 2;
    for (int r0 = 0; r0 < NSUP; r0 += 16) {
        float2 av = *(const float2*)&X[(r0 + rr) * D + i0 + cc];
        As[rr][cc] = av.x; As[rr][cc + 1] = av.y;
        float2 bv = *(const float2*)&X[(r0 + rr) * D + j0 + cc];
        Bs[rr][cc] = bv.x; Bs[rr][cc + 1] = bv.y;
        if (t < 16) Ms[t] = g_mask[r0 + t];
        __syncthreads();
#pragma unroll
        for (int k = 0; k < 16; k++) {
            float mm = Ms[k];
            float ax = As[k][ty * 2], ay = As[k][ty * 2 + 1];
            float bx = Bs[k][tx * 2], by = Bs[k][tx * 2 + 1];
            float p;
            p = ax * bx; aA[0][0] += p; a0[0][0] += mm * p;
            p = ax * by; aA[0][1] += p; a0[0][1] += mm * p;
            p = ay * bx; aA[1][0] += p; a0[1][0] += mm * p;
            p = ay * by; aA[1][1] += p; a0[1][1] += mm * p;
        }
        __syncthreads();
    }
#pragma unroll
    for (int i = 0; i < 2; i++)
#pragma unroll
        for (int j = 0; j < 2; j++) {
            int idx = (i0 + ty * 2 + i) * D + j0 + tx * 2 + j;
            g_G[idx]  = aA[i][j];
            g_G0[idx] = a0[i][j];
        }
}

// ---------------- K4: assemble A_c = lam*cov_c + (1-lam)*task_cov + 0.1 I, accumulate ||A||_F^2 ----------------
__global__ void k_assemble() {
    int c = blockIdx.y;
    int t = blockIdx.x * 256 + threadIdx.x;  // 0 .. D*D-1
    int i = t >> 9, j = t & (D - 1);
    float g  = g_G[t];
    float g0 = g_G0[t];
    float gc = c ? (g - g0) : g0;
    float nc = g_cnt[c];
    float covc = (gc - nc * g_mean[c][i] * g_mean[c][j]) / (nc - 1.f);
    float task = (g - (float)NSUP * g_mall[i] * g_mall[j]) / ((float)NSUP - 1.f);
    float lam = fminf(nc / (nc + 1.f), 0.1f);
    float a = lam * covc + (1.f - lam) * task + ((i == j) ? 0.1f : 0.f);
    g_A[c * D * D + t] = a;
    __shared__ float red[256];
    red[threadIdx.x] = a * a;
    __syncthreads();
    for (int s = 128; s > 0; s >>= 1) {
        if (threadIdx.x < s) red[threadIdx.x] += red[threadIdx.x + s];
        __syncthreads();
    }
    if (threadIdx.x == 0) atomicAdd(&g_fro[c], red[0]);
}

// ---------------- K5: Newton-Schulz init X0 = alpha*I, alpha = 2/(||A||_F + lambda_min) ----------------
__global__ void k_init() {
    int c = blockIdx.y;
    int t = blockIdx.x * 256 + threadIdx.x;
    int i = t >> 9, j = t & (D - 1);
    float alpha = 2.f / (sqrtf(g_fro[c]) + 0.1f);
    g_NS0[c * D * D + t] = (i == j) ? alpha : 0.f;
}

// ---------------- GEMM 512x512x512, batched z=2. mode0: C=A@B; mode1: C=2E-A@B ----------------
__global__ __launch_bounds__(256) void gemm512(const float* __restrict__ A,
                                               const float* __restrict__ B,
                                               const float* __restrict__ E,
                                               float* __restrict__ C, int mode) {
    int off = blockIdx.z * D * D;
    A += off; B += off; E += off; C += off;
    __shared__ float As[16][68], Bs[16][64];
    int t = threadIdx.x;
    int tx = t & 15, ty = t >> 4;
    int i0 = blockIdx.x * 64, j0 = blockIdx.y * 64;
    int ar = t >> 2, ak = (t & 3) * 4;
    int bk = t >> 4, bc = (t & 15) * 4;
    float acc[4][4] = {};
    for (int k0 = 0; k0 < D; k0 += 16) {
        float4 av = *(const float4*)&A[(i0 + ar) * D + k0 + ak];
        As[ak][ar] = av.x; As[ak + 1][ar] = av.y; As[ak + 2][ar] = av.z; As[ak + 3][ar] = av.w;
        *(float4*)&Bs[bk][bc] = *(const float4*)&B[(k0 + bk) * D + j0 + bc];
        __syncthreads();
#pragma unroll
        for (int kk = 0; kk < 16; kk++) {
            float4 a4 = *(const float4*)&As[kk][ty * 4];
            float4 b4 = *(const float4*)&Bs[kk][tx * 4];
            acc[0][0] += a4.x * b4.x; acc[0][1] += a4.x * b4.y; acc[0][2] += a4.x * b4.z; acc[0][3] += a4.x * b4.w;
            acc[1][0] += a4.y * b4.x; acc[1][1] += a4.y * b4.y; acc[1][2] += a4.y * b4.z; acc[1][3] += a4.y * b4.w;
            acc[2][0] += a4.z * b4.x; acc[2][1] += a4.z * b4.y; acc[2][2] += a4.z * b4.z; acc[2][3] += a4.z * b4.w;
            acc[3][0] += a4.w * b4.x; acc[3][1] += a4.w * b4.y; acc[3][2] += a4.w * b4.z; acc[3][3] += a4.w * b4.w;
        }
        __syncthreads();
    }
#pragma unroll
    for (int i = 0; i < 4; i++) {
        int idx = (i0 + ty * 4 + i) * D + j0 + tx * 4;
        float4 r;
        if (mode) {
            float4 e = *(const float4*)&E[idx];
            r.x = 2.f * e.x - acc[i][0]; r.y = 2.f * e.y - acc[i][1];
            r.z = 2.f * e.z - acc[i][2]; r.w = 2.f * e.w - acc[i][3];
        } else {
            r.x = acc[i][0]; r.y = acc[i][1]; r.z = acc[i][2]; r.w = acc[i][3];
        }
        *(float4*)&C[idx] = r;
    }
}

// ---------------- K6: w_c = P_c m_c  (P symmetric -> use column access), b_c = m^T w ----------------
__global__ void k_wb(const float* __restrict__ P) {
    int c = blockIdx.x, i = threadIdx.x;
    const float* Pc = P + c * D * D;
    float w = 0.f;
    for (int j = 0; j < D; j++) w += Pc[j * D + i] * g_mean[c][j];
    g_w[c][i] = w;
    __shared__ float red[D];
    red[i] = w * g_mean[c][i];
    __syncthreads();
    for (int s = 256; s > 0; s >>= 1) {
        if (i < s) red[i] += red[i + s];
        __syncthreads();
    }
    if (i == 0) g_b[c] = red[0];
}

// ---------------- K7: S[c][q] = q^T P_c q  (GEMM Q@P fused with row-dot epilogue) ----------------
__global__ __launch_bounds__(256) void k_main(const float* __restrict__ Q,
                                              const float* __restrict__ P) {
    int c = blockIdx.y;
    const float* Pc = P + c * D * D;
    int q0 = blockIdx.x * 64;
    __shared__ float As[16][68], Bs[16][64];
    __shared__ float red[64][17];
    int t = threadIdx.x;
    int tx = t & 15, ty = t >> 4;
    int ar = t >> 2, ak = (t & 3) * 4;
    int bk = t >> 4, bc = (t & 15) * 4;
    float s[4] = {0.f, 0.f, 0.f, 0.f};
    for (int jt = 0; jt < 8; jt++) {
        int j0 = jt * 64;
        float acc[4][4] = {};
        for (int k0 = 0; k0 < D; k0 += 16) {
            float4 av = *(const float4*)&Q[(q0 + ar) * D + k0 + ak];
            As[ak][ar] = av.x; As[ak + 1][ar] = av.y; As[ak + 2][ar] = av.z; As[ak + 3][ar] = av.w;
            *(float4*)&Bs[bk][bc] = *(const float4*)&Pc[(k0 + bk) * D + j0 + bc];
            __syncthreads();
#pragma unroll
            for (int kk = 0; kk < 16; kk++) {
                float4 a4 = *(const float4*)&As[kk][ty * 4];
                float4 b4 = *(const float4*)&Bs[kk][tx * 4];
                acc[0][0] += a4.x * b4.x; acc[0][1] += a4.x * b4.y; acc[0][2] += a4.x * b4.z; acc[0][3] += a4.x * b4.w;
                acc[1][0] += a4.y * b4.x; acc[1][1] += a4.y * b4.y; acc[1][2] += a4.y * b4.z; acc[1][3] += a4.y * b4.w;
                acc[2][0] += a4.z * b4.x; acc[2][1] += a4.z * b4.y; acc[2][2] += a4.z * b4.z; acc[2][3] += a4.z * b4.w;
                acc[3][0] += a4.w * b4.x; acc[3][1] += a4.w * b4.y; acc[3][2] += a4.w * b4.z; acc[3][3] += a4.w * b4.w;
            }
            __syncthreads();
        }
#pragma unroll
        for (int i = 0; i < 4; i++) {
            float4 qv = *(const float4*)&Q[(q0 + ty * 4 + i) * D + j0 + tx * 4];
            s[i] += acc[i][0] * qv.x + acc[i][1] * qv.y + acc[i][2] * qv.z + acc[i][3] * qv.w;
        }
    }
#pragma unroll
    for (int i = 0; i < 4; i++) red[ty * 4 + i][tx] = s[i];
    __syncthreads();
    if (t < 64) {
        float v = 0.f;
#pragma unroll
        for (int x = 0; x < 16; x++) v += red[t][x];
        g_S[c][q0 + t] = v;
    }
}

// ---------------- K8: logits[q][c] = -(S - 2 q.w_c + b_c) ----------------
__global__ void k_final(const float* __restrict__ Q, float* __restrict__ out, int nq) {
    int w = (blockIdx.x * blockDim.x + threadIdx.x) >> 5;
    int lane = threadIdx.x & 31;
    if (w >= nq) return;
    float qw0 = 0.f, qw1 = 0.f;
    for (int k = lane; k < D; k += 32) {
        float qk = Q[w * D + k];
        qw0 += qk * g_w[0][k];
        qw1 += qk * g_w[1][k];
    }
    for (int o = 16; o > 0; o >>= 1) {
        qw0 += __shfl_down_sync(0xffffffffu, qw0, o);
        qw1 += __shfl_down_sync(0xffffffffu, qw1, o);
    }
    if (lane == 0) {
        out[w * 2 + 0] = -(g_S[0][w] - 2.f * qw0 + g_b[0]);
        out[w * 2 + 1] = -(g_S[1][w] - 2.f * qw1 + g_b[1]);
    }
}

// ---------------- launch ----------------
extern "C" void kernel_launch(void* const* d_in, const int* in_sizes, int n_in,
                              void* d_out, int out_size) {
    const float*        SF   = (const float*)d_in[0];
    const unsigned int* labw = (const unsigned int*)d_in[1];
    const float*        Q    = (const float*)d_in[2];
    float*              out  = (float*)d_out;
    int nq = in_sizes[2] / D;  // 16384

    float *pA, *pX0, *pX1, *pT;
    cudaGetSymbolAddress((void**)&pA,  g_A);
    cudaGetSymbolAddress((void**)&pX0, g_NS0);
    cudaGetSymbolAddress((void**)&pX1, g_NS1);
    cudaGetSymbolAddress((void**)&pT,  g_T);

    k_mask<<<1, NSUP>>>(labw);
    k_sums<<<4, 128>>>(SF);
    k_means<<<2, D>>>();
    k_gram<<<dim3(16, 16), dim3(16, 16)>>>(SF);
    k_assemble<<<dim3(D * D / 256, 2), 256>>>();
    k_init<<<dim3(D * D / 256, 2), 256>>>();

    float* X  = pX0;
    float* Xn = pX1;
    for (int it = 0; it < NITER; it++) {
        // T = X @ A
        gemm512<<<dim3(8, 8, 2), 256>>>(X, pA, X, pT, 0);
        // Xn = 2X - T @ X
        gemm512<<<dim3(8, 8, 2), 256>>>(pT, X, X, Xn, 1);
        float* tmp = X; X = Xn; Xn = tmp;
    }
    // X now holds P_c = A_c^{-1}

    k_wb<<<2, D>>>(X);
    k_main<<<dim3(nq / 64, 2), 256>>>(Q, X);
    k_final<<<(nq * 32 + 255) / 256, 256>>>(Q, out, nq);
}

// round 4
// speedup vs baseline: 1.7882x; 1.7882x over previous
#include <cuda_runtime.h>
#include <cuda_bf16.h>
#include <cstdint>

#define D    512
#define DD   (512 * 512)
#define NSUP 512
#define NQMAX 16384
#define NITER 10

// ---------------- device scratch ----------------
__device__ float g_mask[NSUP];
__device__ float g_cnt[2];
__device__ float g_csum[2][D];
__device__ float g_mall[D];
__device__ float g_mean[2][D];
__device__ float g_G[DD];
__device__ float g_G0[DD];
__device__ float g_A[2 * DD];
__device__ float g_NS0[2 * DD];
__device__ float g_NS1[2 * DD];
__device__ float g_T[2 * DD];
__device__ float g_fro[2];
__device__ float g_w[2][D];
__device__ float g_b[2];
__device__ float g_S[2][NQMAX];
__device__ __nv_bfloat16 g_Qh[NQMAX * D];
__device__ __nv_bfloat16 g_Ql[NQMAX * D];
__device__ __nv_bfloat16 g_Ah[2 * DD];
__device__ __nv_bfloat16 g_Al[2 * DD];
__device__ __nv_bfloat16 g_Th[2 * DD];
__device__ __nv_bfloat16 g_Tl[2 * DD];
__device__ __nv_bfloat16 g_X0h[2 * DD];
__device__ __nv_bfloat16 g_X0l[2 * DD];
__device__ __nv_bfloat16 g_X1h[2 * DD];
__device__ __nv_bfloat16 g_X1l[2 * DD];

// ---------------- helpers ----------------
__device__ __forceinline__ uint32_t smem_u32(const void* p) {
    uint32_t a;
    asm("{ .reg .u64 t; cvta.to.shared.u64 t, %1; cvt.u32.u64 %0, t; }" : "=r"(a) : "l"(p));
    return a;
}
__device__ __forceinline__ void mma16816(float* d, const uint32_t* a, const uint32_t* b) {
    asm volatile(
        "mma.sync.aligned.m16n8k16.row.col.f32.bf16.bf16.f32 "
        "{%0,%1,%2,%3}, {%4,%5,%6,%7}, {%8,%9}, {%0,%1,%2,%3};"
        : "+f"(d[0]), "+f"(d[1]), "+f"(d[2]), "+f"(d[3])
        : "r"(a[0]), "r"(a[1]), "r"(a[2]), "r"(a[3]), "r"(b[0]), "r"(b[1]));
}
__device__ __forceinline__ void ldm4(uint32_t* r, uint32_t addr) {
    asm volatile("ldmatrix.sync.aligned.m8n8.x4.shared.b16 {%0,%1,%2,%3}, [%4];"
                 : "=r"(r[0]), "=r"(r[1]), "=r"(r[2]), "=r"(r[3]) : "r"(addr));
}
__device__ __forceinline__ void bf16split2(float v0, float v1, unsigned int& hh, unsigned int& ll) {
    __nv_bfloat16 h0 = __float2bfloat16(v0), h1 = __float2bfloat16(v1);
    __nv_bfloat16 l0 = __float2bfloat16(v0 - __bfloat162float(h0));
    __nv_bfloat16 l1 = __float2bfloat16(v1 - __bfloat162float(h1));
    hh = ((unsigned int)*(unsigned short*)&h0) | (((unsigned int)*(unsigned short*)&h1) << 16);
    ll = ((unsigned int)*(unsigned short*)&l0) | (((unsigned int)*(unsigned short*)&l1) << 16);
}

// ---------------- K0: label mask (int32 vs int64 robust) ----------------
__global__ void k_mask(const unsigned int* __restrict__ labw) {
    __shared__ int oddOr;
    int i = threadIdx.x;
    if (i == 0) oddOr = 0;
    __syncthreads();
    unsigned int w = labw[i];
    if ((i & 1) && w) atomicOr(&oddOr, 1);
    __syncthreads();
    unsigned int li = oddOr ? labw[i] : labw[2 * i];
    g_mask[i] = (li == 0) ? 1.f : 0.f;
}

// ---------------- K1: per-class sums + overall mean + counts ----------------
__global__ void k_sums(const float* __restrict__ X) {
    __shared__ float m[NSUP];
    int t = threadIdx.x;
    for (int i = t; i < NSUP; i += 128) m[i] = g_mask[i];
    __syncthreads();
    int j = blockIdx.x * 128 + t;
    float sa = 0.f, s0 = 0.f;
    for (int i = 0; i < NSUP; i++) {
        float x = X[i * D + j];
        sa += x; s0 += m[i] * x;
    }
    g_mall[j] = sa / (float)NSUP;
    g_csum[0][j] = s0;
    g_csum[1][j] = sa - s0;
    if (blockIdx.x == 0 && t < 32) {
        float c0 = 0.f;
        for (int i = t; i < NSUP; i += 32) c0 += m[i];
        for (int o = 16; o > 0; o >>= 1) c0 += __shfl_down_sync(0xffffffffu, c0, o);
        if (t == 0) { g_cnt[0] = c0; g_cnt[1] = (float)NSUP - c0; }
    }
}

__global__ void k_means() {
    int c = blockIdx.x, j = threadIdx.x;
    g_mean[c][j] = g_csum[c][j] / g_cnt[c];
    if (j == 0) g_fro[c] = 0.f;
}

// ---------------- K3: Gram matrices ----------------
__global__ void k_gram(const float* __restrict__ X) {
    __shared__ float As[16][33], Bs[16][33], Ms[16];
    int tx = threadIdx.x, ty = threadIdx.y;
    int t = ty * 16 + tx;
    int i0 = blockIdx.x * 32, j0 = blockIdx.y * 32;
    float aA[2][2] = {}, a0[2][2] = {};
    int rr = t >> 4, cc = (t & 15) * 2;
    for (int r0 = 0; r0 < NSUP; r0 += 16) {
        float2 av = *(const float2*)&X[(r0 + rr) * D + i0 + cc];
        As[rr][cc] = av.x; As[rr][cc + 1] = av.y;
        float2 bv = *(const float2*)&X[(r0 + rr) * D + j0 + cc];
        Bs[rr][cc] = bv.x; Bs[rr][cc + 1] = bv.y;
        if (t < 16) Ms[t] = g_mask[r0 + t];
        __syncthreads();
#pragma unroll
        for (int k = 0; k < 16; k++) {
            float mm = Ms[k];
            float ax = As[k][ty * 2], ay = As[k][ty * 2 + 1];
            float bx = Bs[k][tx * 2], by = Bs[k][tx * 2 + 1];
            float p;
            p = ax * bx; aA[0][0] += p; a0[0][0] += mm * p;
            p = ax * by; aA[0][1] += p; a0[0][1] += mm * p;
            p = ay * bx; aA[1][0] += p; a0[1][0] += mm * p;
            p = ay * by; aA[1][1] += p; a0[1][1] += mm * p;
        }
        __syncthreads();
    }
#pragma unroll
    for (int i = 0; i < 2; i++)
#pragma unroll
        for (int j = 0; j < 2; j++) {
            int idx = (i0 + ty * 2 + i) * D + j0 + tx * 2 + j;
            g_G[idx] = aA[i][j];
            g_G0[idx] = a0[i][j];
        }
}

// ---------------- K4: assemble A_c (+ write bf16 hi/lo split of A) ----------------
__global__ void k_assemble() {
    int c = blockIdx.y;
    int t = blockIdx.x * 256 + threadIdx.x;
    int i = t >> 9, j = t & (D - 1);
    float g = g_G[t], g0 = g_G0[t];
    float gc = c ? (g - g0) : g0;
    float nc = g_cnt[c];
    float covc = (gc - nc * g_mean[c][i] * g_mean[c][j]) / (nc - 1.f);
    float task = (g - (float)NSUP * g_mall[i] * g_mall[j]) / ((float)NSUP - 1.f);
    float lam = fminf(nc / (nc + 1.f), 0.1f);
    float a = lam * covc + (1.f - lam) * task + ((i == j) ? 0.1f : 0.f);
    int idx = c * DD + t;
    g_A[idx] = a;
    __nv_bfloat16 h = __float2bfloat16(a);
    g_Ah[idx] = h;
    g_Al[idx] = __float2bfloat16(a - __bfloat162float(h));
}

// ---------------- K4b: Frobenius^2 of A^4 (spectral upper bound) ----------------
__global__ void k_fro4(const float* __restrict__ M4) {
    int c = blockIdx.y;
    int t = blockIdx.x * 256 + threadIdx.x;
    float a = M4[c * DD + t];
    __shared__ float red[256];
    red[threadIdx.x] = a * a;
    __syncthreads();
    for (int s = 128; s > 0; s >>= 1) {
        if (threadIdx.x < s) red[threadIdx.x] += red[threadIdx.x + s];
        __syncthreads();
    }
    if (threadIdx.x == 0) atomicAdd(&g_fro[c], red[0]);
}

// ---------------- K5: NS init X0 = alpha*I (+ split) ----------------
__global__ void k_init() {
    int c = blockIdx.y;
    int t = blockIdx.x * 256 + threadIdx.x;
    int i = t >> 9, j = t & (D - 1);
    float lub = powf(g_fro[c], 0.125f);  // (sum lambda^8)^(1/8) >= lambda_max
    float alpha = 2.f / (lub + 0.1f);
    float v = (i == j) ? alpha : 0.f;
    int idx = c * DD + t;
    g_NS0[idx] = v;
    __nv_bfloat16 h = __float2bfloat16(v);
    g_X0h[idx] = h;
    g_X0l[idx] = __float2bfloat16(v - __bfloat162float(h));
}

// ---------------- SIMT GEMM 512^3 (spectral bound only) ----------------
__global__ __launch_bounds__(256) void gemm512(const float* __restrict__ A,
                                               const float* __restrict__ B,
                                               float* __restrict__ C) {
    int off = blockIdx.z * DD;
    A += off; B += off; C += off;
    __shared__ float As[16][68], Bs[16][64];
    int t = threadIdx.x;
    int tx = t & 15, ty = t >> 4;
    int i0 = blockIdx.x * 64, j0 = blockIdx.y * 64;
    int ar = t >> 2, ak = (t & 3) * 4;
    int bk = t >> 4, bc = (t & 15) * 4;
    float acc[4][4] = {};
    for (int k0 = 0; k0 < D; k0 += 16) {
        float4 av = *(const float4*)&A[(i0 + ar) * D + k0 + ak];
        As[ak][ar] = av.x; As[ak + 1][ar] = av.y; As[ak + 2][ar] = av.z; As[ak + 3][ar] = av.w;
        *(float4*)&Bs[bk][bc] = *(const float4*)&B[(k0 + bk) * D + j0 + bc];
        __syncthreads();
#pragma unroll
        for (int kk = 0; kk < 16; kk++) {
            float4 a4 = *(const float4*)&As[kk][ty * 4];
            float4 b4 = *(const float4*)&Bs[kk][tx * 4];
            acc[0][0] += a4.x * b4.x; acc[0][1] += a4.x * b4.y; acc[0][2] += a4.x * b4.z; acc[0][3] += a4.x * b4.w;
            acc[1][0] += a4.y * b4.x; acc[1][1] += a4.y * b4.y; acc[1][2] += a4.y * b4.z; acc[1][3] += a4.y * b4.w;
            acc[2][0] += a4.z * b4.x; acc[2][1] += a4.z * b4.y; acc[2][2] += a4.z * b4.z; acc[2][3] += a4.z * b4.w;
            acc[3][0] += a4.w * b4.x; acc[3][1] += a4.w * b4.y; acc[3][2] += a4.w * b4.z; acc[3][3] += a4.w * b4.w;
        }
        __syncthreads();
    }
#pragma unroll
    for (int i = 0; i < 4; i++) {
        int idx = (i0 + ty * 4 + i) * D + j0 + tx * 4;
        float4 r;
        r.x = acc[i][0]; r.y = acc[i][1]; r.z = acc[i][2]; r.w = acc[i][3];
        *(float4*)&C[idx] = r;
    }
}

// ---------------- NS GEMM via mma.sync, bf16-split, fused output split ----------------
// C = A@B (mode 0) or C = 2E - A@B (mode 1); also writes Ch/Cl = bf16 hi/lo of C.
// A,B symmetric (B fed by rows). Virtual K = 3 phases: Ah*Bh, Ah*Bl, Al*Bh.
#define NS_BUF 10240  // A: 64 rows x 80B (5120) + B: 64 x 80B
__global__ __launch_bounds__(256) void gemm_ns(
    const __nv_bfloat16* __restrict__ Ahp, const __nv_bfloat16* __restrict__ Alp,
    const __nv_bfloat16* __restrict__ Bhp, const __nv_bfloat16* __restrict__ Blp,
    const float* __restrict__ E, float* __restrict__ C,
    __nv_bfloat16* __restrict__ Ch, __nv_bfloat16* __restrict__ Cl, int mode) {
    __shared__ char sm[2 * NS_BUF];
    size_t zo = (size_t)blockIdx.z * DD;
    const char* Ah8 = (const char*)(Ahp + zo);
    const char* Al8 = (const char*)(Alp + zo);
    const char* Bh8 = (const char*)(Bhp + zo);
    const char* Bl8 = (const char*)(Blp + zo);
    E += zo; C += zo; Ch += zo; Cl += zo;
    uint32_t smb = smem_u32(sm);
    int tid = threadIdx.x, lane = tid & 31, wid = tid >> 5;
    int warp_m = (wid & 1) * 32, warp_n = (wid >> 1) * 16;
    int i0 = blockIdx.x * 64, j0 = blockIdx.y * 64;
    int r0 = tid >> 2, cseg = (tid & 3) * 16;

    float d[2][2][4];
#pragma unroll
    for (int a = 0; a < 2; a++)
#pragma unroll
        for (int b = 0; b < 2; b++)
#pragma unroll
            for (int k = 0; k < 4; k++) d[a][b][k] = 0.f;

    uint4 ra, rb;
#define NS_LOAD(c) do { \
        int p = (c) >> 4; int kb = ((c) & 15) * 64 + cseg; \
        const char* Asrc = (p == 2) ? Al8 : Ah8; \
        const char* Bsrc = (p == 1) ? Bl8 : Bh8; \
        ra = *(const uint4*)(Asrc + (size_t)(i0 + r0) * 1024 + kb); \
        rb = *(const uint4*)(Bsrc + (size_t)(j0 + r0) * 1024 + kb); \
    } while (0)
#define NS_STS(buf) do { \
        *(uint4*)(sm + (buf) * NS_BUF + r0 * 80 + cseg) = ra; \
        *(uint4*)(sm + (buf) * NS_BUF + 5120 + r0 * 80 + cseg) = rb; \
    } while (0)

    NS_LOAD(0); NS_STS(0);
    __syncthreads();
    for (int c = 0; c < 48; c++) {
        int cur = c & 1;
        if (c < 47) NS_LOAD(c + 1);
        uint32_t baseA = smb + cur * NS_BUF;
        uint32_t baseB = baseA + 5120;
#pragma unroll
        for (int ks = 0; ks < 2; ks++) {
            uint32_t afr[2][4], bfr[2][2], r4[4];
#pragma unroll
            for (int mi = 0; mi < 2; mi++)
                ldm4(afr[mi], baseA + (warp_m + mi * 16 + (lane & 15)) * 80 + (lane >> 4) * 16 + ks * 32);
            ldm4(r4, baseB + (warp_n + ((lane >> 4) & 1) * 8 + (lane & 7)) * 80 + ((lane >> 3) & 1) * 16 + ks * 32);
            bfr[0][0] = r4[0]; bfr[0][1] = r4[1]; bfr[1][0] = r4[2]; bfr[1][1] = r4[3];
#pragma unroll
            for (int mi = 0; mi < 2; mi++)
#pragma unroll
                for (int ni = 0; ni < 2; ni++)
                    mma16816(d[mi][ni], afr[mi], bfr[ni]);
        }
        if (c < 47) NS_STS(1 - cur);
        __syncthreads();
    }
    // epilogue: write C fp32 + bf16 split
#pragma unroll
    for (int mi = 0; mi < 2; mi++)
#pragma unroll
        for (int ni = 0; ni < 2; ni++) {
            int col = j0 + warp_n + ni * 8 + 2 * (lane & 3);
#pragma unroll
            for (int h = 0; h < 2; h++) {
                int row = i0 + warp_m + mi * 16 + h * 8 + (lane >> 2);
                size_t idx = (size_t)row * D + col;
                float v0 = d[mi][ni][2 * h], v1 = d[mi][ni][2 * h + 1];
                if (mode) {
                    float2 e = *(const float2*)&E[idx];
                    v0 = 2.f * e.x - v0; v1 = 2.f * e.y - v1;
                }
                *(float2*)&C[idx] = make_float2(v0, v1);
                unsigned int hh, ll;
                bf16split2(v0, v1, hh, ll);
                *(unsigned int*)&Ch[idx] = hh;
                *(unsigned int*)&Cl[idx] = ll;
            }
        }
#undef NS_LOAD
#undef NS_STS
}

// ---------------- K6: w_c = P_c m_c, b_c = m^T w ----------------
__global__ void k_wb(const float* __restrict__ P) {
    int c = blockIdx.x, i = threadIdx.x;
    const float* Pc = P + (size_t)c * DD;
    float w = 0.f;
    for (int j = 0; j < D; j++) w += Pc[j * D + i] * g_mean[c][j];
    g_w[c][i] = w;
    __shared__ float red[D];
    red[i] = w * g_mean[c][i];
    __syncthreads();
    for (int s = 256; s > 0; s >>= 1) {
        if (i < s) red[i] += red[i + s];
        __syncthreads();
    }
    if (i == 0) g_b[c] = red[0];
}

// ---------------- Q split fp32 -> bf16 hi/lo ----------------
__global__ void k_split(const float* __restrict__ S, __nv_bfloat16* __restrict__ H,
                        __nv_bfloat16* __restrict__ L) {
    int i = blockIdx.x * 256 + threadIdx.x;
    float4 v = ((const float4*)S)[i];
    uint2 hh, ll;
    bf16split2(v.x, v.y, hh.x, ll.x);
    bf16split2(v.z, v.w, hh.y, ll.y);
    ((uint2*)H)[i] = hh;
    ((uint2*)L)[i] = ll;
}

// ---------------- K7: main pass S[c][q] = q^T P_c q via mma.sync ----------------
#define MB_BUF 20480  // A: 128 x 80B (10240) + B: 128 x 80B
__global__ __launch_bounds__(256, 2) void k_main_mma(
    const float* __restrict__ Q,
    const __nv_bfloat16* __restrict__ Qh, const __nv_bfloat16* __restrict__ Ql,
    const __nv_bfloat16* __restrict__ Phg, const __nv_bfloat16* __restrict__ Plg) {
    extern __shared__ char sm[];
    __shared__ float sRow[128][2];
    int cls = blockIdx.y;
    const char* Ph8 = (const char*)(Phg + (size_t)cls * DD);
    const char* Pl8 = (const char*)(Plg + (size_t)cls * DD);
    const char* Qh8 = (const char*)Qh;
    const char* Ql8 = (const char*)Ql;
    uint32_t smb = smem_u32(sm);
    int tid = threadIdx.x, lane = tid & 31, wid = tid >> 5;
    int warp_m = (wid >> 1) * 32, warp_n = (wid & 1) * 64;
    int q0 = blockIdx.x * 128;
    int r0 = tid >> 2, cseg = (tid & 3) * 16;
    float accS[4] = {0.f, 0.f, 0.f, 0.f};
    uint4 ra0, ra1, rb0, rb1;

#define MB_LOAD(c, n0) do { \
        int p = (c) >> 4; int kb = ((c) & 15) * 64 + cseg; \
        const char* Asrc = (p == 2) ? Ql8 : Qh8; \
        const char* Bsrc = (p == 1) ? Pl8 : Ph8; \
        ra0 = *(const uint4*)(Asrc + (size_t)(q0 + r0) * 1024 + kb); \
        ra1 = *(const uint4*)(Asrc + (size_t)(q0 + 64 + r0) * 1024 + kb); \
        rb0 = *(const uint4*)(Bsrc + (size_t)((n0) + r0) * 1024 + kb); \
        rb1 = *(const uint4*)(Bsrc + (size_t)((n0) + 64 + r0) * 1024 + kb); \
    } while (0)
#define MB_STS(buf) do { \
        char* dA = sm + (buf) * MB_BUF + r0 * 80 + cseg; \
        *(uint4*)dA = ra0; *(uint4*)(dA + 64 * 80) = ra1; \
        char* dB = sm + (buf) * MB_BUF + 10240 + r0 * 80 + cseg; \
        *(uint4*)dB = rb0; *(uint4*)(dB + 64 * 80) = rb1; \
    } while (0)

    for (int nt = 0; nt < 4; nt++) {
        int n0 = nt * 128;
        float d[2][8][4];
#pragma unroll
        for (int a = 0; a < 2; a++)
#pragma unroll
            for (int b = 0; b < 8; b++)
#pragma unroll
                for (int k = 0; k < 4; k++) d[a][b][k] = 0.f;
        MB_LOAD(0, n0); MB_STS(0);
        __syncthreads();
        for (int c = 0; c < 48; c++) {
            int cur = c & 1;
            if (c < 47) MB_LOAD(c + 1, n0);
            uint32_t baseA = smb + cur * MB_BUF;
            uint32_t baseB = baseA + 10240;
#pragma unroll
            for (int ks = 0; ks < 2; ks++) {
                uint32_t afr[2][4], bfr[8][2], r4[4];
#pragma unroll
                for (int mi = 0; mi < 2; mi++)
                    ldm4(afr[mi], baseA + (warp_m + mi * 16 + (lane & 15)) * 80 + (lane >> 4) * 16 + ks * 32);
#pragma unroll
                for (int j = 0; j < 4; j++) {
                    ldm4(r4, baseB + (warp_n + j * 16 + ((lane >> 4) & 1) * 8 + (lane & 7)) * 80 + ((lane >> 3) & 1) * 16 + ks * 32);
                    bfr[2 * j][0] = r4[0]; bfr[2 * j][1] = r4[1];
                    bfr[2 * j + 1][0] = r4[2]; bfr[2 * j + 1][1] = r4[3];
                }
#pragma unroll
                for (int mi = 0; mi < 2; mi++)
#pragma unroll
                    for (int ni = 0; ni < 8; ni++)
                        mma16816(d[mi][ni], afr[mi], bfr[ni]);
            }
            if (c < 47) MB_STS(1 - cur);
            __syncthreads();
        }
        // fused dot with fp32 Q
#pragma unroll
        for (int mi = 0; mi < 2; mi++)
#pragma unroll
            for (int h = 0; h < 2; h++) {
                int row = q0 + warp_m + mi * 16 + h * 8 + (lane >> 2);
                float a = 0.f;
#pragma unroll
                for (int ni = 0; ni < 8; ni++) {
                    int col = n0 + warp_n + ni * 8 + 2 * (lane & 3);
                    float2 qv = *(const float2*)&Q[(size_t)row * D + col];
                    a += d[mi][ni][2 * h] * qv.x + d[mi][ni][2 * h + 1] * qv.y;
                }
                accS[mi * 2 + h] += a;
            }
    }
#pragma unroll
    for (int i = 0; i < 4; i++) {
        accS[i] += __shfl_xor_sync(0xffffffffu, accS[i], 1);
        accS[i] += __shfl_xor_sync(0xffffffffu, accS[i], 2);
    }
    if ((lane & 3) == 0) {
#pragma unroll
        for (int mi = 0; mi < 2; mi++)
#pragma unroll
            for (int h = 0; h < 2; h++)
                sRow[warp_m + mi * 16 + h * 8 + (lane >> 2)][wid & 1] = accS[mi * 2 + h];
    }
    __syncthreads();
    if (tid < 128) g_S[cls][q0 + tid] = sRow[tid][0] + sRow[tid][1];
#undef MB_LOAD
#undef MB_STS
}

// ---------------- K8: logits ----------------
__global__ void k_final(const float* __restrict__ Q, float* __restrict__ out, int nq) {
    int w = (blockIdx.x * blockDim.x + threadIdx.x) >> 5;
    int lane = threadIdx.x & 31;
    if (w >= nq) return;
    float qw0 = 0.f, qw1 = 0.f;
    for (int k = lane; k < D; k += 32) {
        float qk = Q[w * D + k];
        qw0 += qk * g_w[0][k];
        qw1 += qk * g_w[1][k];
    }
    for (int o = 16; o > 0; o >>= 1) {
        qw0 += __shfl_down_sync(0xffffffffu, qw0, o);
        qw1 += __shfl_down_sync(0xffffffffu, qw1, o);
    }
    if (lane == 0) {
        out[w * 2 + 0] = -(g_S[0][w] - 2.f * qw0 + g_b[0]);
        out[w * 2 + 1] = -(g_S[1][w] - 2.f * qw1 + g_b[1]);
    }
}

// ---------------- launch ----------------
extern "C" void kernel_launch(void* const* d_in, const int* in_sizes, int n_in,
                              void* d_out, int out_size) {
    const float*        SF   = (const float*)d_in[0];
    const unsigned int* labw = (const unsigned int*)d_in[1];
    const float*        Q    = (const float*)d_in[2];
    float*              out  = (float*)d_out;
    int nq = in_sizes[2] / D;  // 16384

    float *pA, *pX0, *pX1, *pT;
    __nv_bfloat16 *pQh, *pQl, *pAh, *pAl, *pTh, *pTl, *pXh0, *pXl0, *pXh1, *pXl1;
    cudaGetSymbolAddress((void**)&pA, g_A);
    cudaGetSymbolAddress((void**)&pX0, g_NS0);
    cudaGetSymbolAddress((void**)&pX1, g_NS1);
    cudaGetSymbolAddress((void**)&pT, g_T);
    cudaGetSymbolAddress((void**)&pQh, g_Qh);
    cudaGetSymbolAddress((void**)&pQl, g_Ql);
    cudaGetSymbolAddress((void**)&pAh, g_Ah);
    cudaGetSymbolAddress((void**)&pAl, g_Al);
    cudaGetSymbolAddress((void**)&pTh, g_Th);
    cudaGetSymbolAddress((void**)&pTl, g_Tl);
    cudaGetSymbolAddress((void**)&pXh0, g_X0h);
    cudaGetSymbolAddress((void**)&pXl0, g_X0l);
    cudaGetSymbolAddress((void**)&pXh1, g_X1h);
    cudaGetSymbolAddress((void**)&pXl1, g_X1l);
    cudaFuncSetAttribute(k_main_mma, cudaFuncAttributeMaxDynamicSharedMemorySize, 2 * MB_BUF);

    k_mask<<<1, NSUP>>>(labw);
    k_sums<<<4, 128>>>(SF);
    k_means<<<2, D>>>();
    k_gram<<<dim3(16, 16), dim3(16, 16)>>>(SF);
    k_assemble<<<dim3(DD / 256, 2), 256>>>();
    // spectral bound: M2 = A@A, M4 = M2@M2, fro(M4)
    gemm512<<<dim3(8, 8, 2), 256>>>(pA, pA, pT);
    gemm512<<<dim3(8, 8, 2), 256>>>(pT, pT, pX1);
    k_fro4<<<dim3(DD / 256, 2), 256>>>(pX1);
    k_init<<<dim3(DD / 256, 2), 256>>>();

    float *X = pX0, *Xn = pX1;
    __nv_bfloat16 *Xh = pXh0, *Xl = pXl0, *Xnh = pXh1, *Xnl = pXl1;
    dim3 gns(8, 8, 2);
    for (int it = 0; it < NITER; it++) {
        // T = X @ A (+ split of T)
        gemm_ns<<<gns, 256>>>(Xh, Xl, pAh, pAl, pT, pT, pTh, pTl, 0);
        // Xn = 2X - T @ X (+ split of Xn)
        gemm_ns<<<gns, 256>>>(pTh, pTl, Xh, Xl, X, Xn, Xnh, Xnl, 1);
        float* tf = X; X = Xn; Xn = tf;
        __nv_bfloat16* tb;
        tb = Xh; Xh = Xnh; Xnh = tb;
        tb = Xl; Xl = Xnl; Xnl = tb;
    }
    // X / Xh / Xl now hold P_c and its bf16 split

    k_wb<<<2, D>>>(X);
    k_split<<<(nq * D) / 1024, 256>>>(Q, pQh, pQl);
    k_main_mma<<<dim3(nq / 128, 2), 256, 2 * MB_BUF>>>(Q, pQh, pQl, Xh, Xl);
    k_final<<<(nq * 32 + 255) / 256, 256>>>(Q, out, nq);
}

// round 5
// speedup vs baseline: 2.3836x; 1.3329x over previous
#include <cuda_runtime.h>
#include <cuda_bf16.h>
#include <cstdint>

#define D    512
#define DD   (512 * 512)
#define NSUP 512
#define NQMAX 16384
#define NIT_CHEAP 8
#define NIT_FULL  2

// ---------------- device scratch ----------------
__device__ float g_mask[NSUP];
__device__ float g_cnt[2];
__device__ float g_csum[2][D];
__device__ float g_mall[D];
__device__ float g_mean[2][D];
__device__ float g_G[DD];
__device__ float g_G0[DD];
__device__ float g_A[2 * DD];
__device__ float g_NS0[2 * DD];
__device__ float g_NS1[2 * DD];
__device__ float g_T[2 * DD];
__device__ float g_fro[2];
__device__ float g_w[2][D];
__device__ float g_b[2];
__device__ float g_S[2][NQMAX];
__device__ __nv_bfloat16 g_Qh[NQMAX * D];
__device__ __nv_bfloat16 g_Ql[NQMAX * D];
__device__ __nv_bfloat16 g_Ah[2 * DD];
__device__ __nv_bfloat16 g_Al[2 * DD];
__device__ __nv_bfloat16 g_Th[2 * DD];
__device__ __nv_bfloat16 g_Tl[2 * DD];
__device__ __nv_bfloat16 g_X0h[2 * DD];
__device__ __nv_bfloat16 g_X0l[2 * DD];
__device__ __nv_bfloat16 g_X1h[2 * DD];
__device__ __nv_bfloat16 g_X1l[2 * DD];

// ---------------- helpers ----------------
__device__ __forceinline__ uint32_t smem_u32(const void* p) {
    uint32_t a;
    asm("{ .reg .u64 t; cvta.to.shared.u64 t, %1; cvt.u32.u64 %0, t; }" : "=r"(a) : "l"(p));
    return a;
}
__device__ __forceinline__ void mma16816(float* d, const uint32_t* a, const uint32_t* b) {
    asm volatile(
        "mma.sync.aligned.m16n8k16.row.col.f32.bf16.bf16.f32 "
        "{%0,%1,%2,%3}, {%4,%5,%6,%7}, {%8,%9}, {%0,%1,%2,%3};"
        : "+f"(d[0]), "+f"(d[1]), "+f"(d[2]), "+f"(d[3])
        : "r"(a[0]), "r"(a[1]), "r"(a[2]), "r"(a[3]), "r"(b[0]), "r"(b[1]));
}
__device__ __forceinline__ void ldm4(uint32_t* r, uint32_t addr) {
    asm volatile("ldmatrix.sync.aligned.m8n8.x4.shared.b16 {%0,%1,%2,%3}, [%4];"
                 : "=r"(r[0]), "=r"(r[1]), "=r"(r[2]), "=r"(r[3]) : "r"(addr));
}
__device__ __forceinline__ void ldm4t(uint32_t* r, uint32_t addr) {
    asm volatile("ldmatrix.sync.aligned.m8n8.x4.trans.shared.b16 {%0,%1,%2,%3}, [%4];"
                 : "=r"(r[0]), "=r"(r[1]), "=r"(r[2]), "=r"(r[3]) : "r"(addr));
}
__device__ __forceinline__ void bf16split2(float v0, float v1, unsigned int& hh, unsigned int& ll) {
    __nv_bfloat16 h0 = __float2bfloat16(v0), h1 = __float2bfloat16(v1);
    __nv_bfloat16 l0 = __float2bfloat16(v0 - __bfloat162float(h0));
    __nv_bfloat16 l1 = __float2bfloat16(v1 - __bfloat162float(h1));
    hh = ((unsigned int)*(unsigned short*)&h0) | (((unsigned int)*(unsigned short*)&h1) << 16);
    ll = ((unsigned int)*(unsigned short*)&l0) | (((unsigned int)*(unsigned short*)&l1) << 16);
}

// ---------------- K0: label mask + count + zero accumulators ----------------
__global__ void k_mask(const unsigned int* __restrict__ labw) {
    __shared__ int oddOr;
    __shared__ float red[NSUP];
    int i = threadIdx.x;
    if (i == 0) oddOr = 0;
    __syncthreads();
    unsigned int w = labw[i];
    if ((i & 1) && w) atomicOr(&oddOr, 1);
    __syncthreads();
    unsigned int li = oddOr ? labw[i] : labw[2 * i];
    float mv = (li == 0) ? 1.f : 0.f;
    g_mask[i] = mv;
    g_csum[0][i] = 0.f;
    g_csum[1][i] = 0.f;
    g_mall[i] = 0.f;
    if (i < 2) g_fro[i] = 0.f;
    red[i] = mv;
    __syncthreads();
    for (int s = 256; s > 0; s >>= 1) {
        if (i < s) red[i] += red[i + s];
        __syncthreads();
    }
    if (i == 0) { g_cnt[0] = red[0]; g_cnt[1] = (float)NSUP - red[0]; }
}

// ---------------- K1: per-class sums (parallel, atomics) ----------------
__global__ void k_sums(const float* __restrict__ X) {
    __shared__ float m[128];
    int t = threadIdx.x;  // 128
    int rb = blockIdx.y * 128;
    m[t] = g_mask[rb + t];
    __syncthreads();
    int j = blockIdx.x * 128 + t;
    float sa = 0.f, s0 = 0.f;
    for (int r = 0; r < 128; r++) {
        float x = X[(size_t)(rb + r) * D + j];
        sa += x; s0 += m[r] * x;
    }
    atomicAdd(&g_mall[j], sa);
    atomicAdd(&g_csum[0][j], s0);
    atomicAdd(&g_csum[1][j], sa - s0);
}

__global__ void k_means() {
    int c = blockIdx.x, j = threadIdx.x;
    if (c == 0) g_mall[j] *= (1.f / (float)NSUP);
    g_mean[c][j] = g_csum[c][j] / g_cnt[c];
}

// ---------------- K3: Gram matrices ----------------
__global__ void k_gram(const float* __restrict__ X) {
    __shared__ float As[16][33], Bs[16][33], Ms[16];
    int tx = threadIdx.x, ty = threadIdx.y;
    int t = ty * 16 + tx;
    int i0 = blockIdx.x * 32, j0 = blockIdx.y * 32;
    float aA[2][2] = {}, a0[2][2] = {};
    int rr = t >> 4, cc = (t & 15) * 2;
    for (int r0 = 0; r0 < NSUP; r0 += 16) {
        float2 av = *(const float2*)&X[(r0 + rr) * D + i0 + cc];
        As[rr][cc] = av.x; As[rr][cc + 1] = av.y;
        float2 bv = *(const float2*)&X[(r0 + rr) * D + j0 + cc];
        Bs[rr][cc] = bv.x; Bs[rr][cc + 1] = bv.y;
        if (t < 16) Ms[t] = g_mask[r0 + t];
        __syncthreads();
#pragma unroll
        for (int k = 0; k < 16; k++) {
            float mm = Ms[k];
            float ax = As[k][ty * 2], ay = As[k][ty * 2 + 1];
            float bx = Bs[k][tx * 2], by = Bs[k][tx * 2 + 1];
            float p;
            p = ax * bx; aA[0][0] += p; a0[0][0] += mm * p;
            p = ax * by; aA[0][1] += p; a0[0][1] += mm * p;
            p = ay * bx; aA[1][0] += p; a0[1][0] += mm * p;
            p = ay * by; aA[1][1] += p; a0[1][1] += mm * p;
        }
        __syncthreads();
    }
#pragma unroll
    for (int i = 0; i < 2; i++)
#pragma unroll
        for (int j = 0; j < 2; j++) {
            int idx = (i0 + ty * 2 + i) * D + j0 + tx * 2 + j;
            g_G[idx] = aA[i][j];
            g_G0[idx] = a0[i][j];
        }
}

// ---------------- K4: assemble A_c (+ bf16 split) ----------------
__global__ void k_assemble() {
    int c = blockIdx.y;
    int t = blockIdx.x * 256 + threadIdx.x;
    int i = t >> 9, j = t & (D - 1);
    float g = g_G[t], g0 = g_G0[t];
    float gc = c ? (g - g0) : g0;
    float nc = g_cnt[c];
    float covc = (gc - nc * g_mean[c][i] * g_mean[c][j]) / (nc - 1.f);
    float task = (g - (float)NSUP * g_mall[i] * g_mall[j]) / ((float)NSUP - 1.f);
    float lam = fminf(nc / (nc + 1.f), 0.1f);
    float a = lam * covc + (1.f - lam) * task + ((i == j) ? 0.1f : 0.f);
    int idx = c * DD + t;
    g_A[idx] = a;
    __nv_bfloat16 h = __float2bfloat16(a);
    g_Ah[idx] = h;
    g_Al[idx] = __float2bfloat16(a - __bfloat162float(h));
}

// ---------------- K4b: Frobenius^2 of A^4 ----------------
__global__ void k_fro4(const float* __restrict__ M4) {
    int c = blockIdx.y;
    int t = blockIdx.x * 256 + threadIdx.x;
    float a = M4[(size_t)c * DD + t];
    __shared__ float red[256];
    red[threadIdx.x] = a * a;
    __syncthreads();
    for (int s = 128; s > 0; s >>= 1) {
        if (threadIdx.x < s) red[threadIdx.x] += red[threadIdx.x + s];
        __syncthreads();
    }
    if (threadIdx.x == 0) atomicAdd(&g_fro[c], red[0]);
}

// ---------------- K5: NS init X0 = alpha*I (+ split) ----------------
__global__ void k_init() {
    int c = blockIdx.y;
    int t = blockIdx.x * 256 + threadIdx.x;
    int i = t >> 9, j = t & (D - 1);
    float lub = 1.02f * powf(g_fro[c], 0.125f) + 0.02f;  // safe upper bound on lambda_max
    float alpha = 2.f / (lub + 0.1f);
    float v = (i == j) ? alpha : 0.f;
    int idx = c * DD + t;
    g_NS0[idx] = v;
    __nv_bfloat16 h = __float2bfloat16(v);
    g_X0h[idx] = h;
    g_X0l[idx] = __float2bfloat16(v - __bfloat162float(h));
}

// ---------------- NS GEMM: C = A@B (mode0) or 2E - A@B (mode1), + bf16 split out ----------------
// A-operand fed by rows (row-major); B-operand fed as TRUE transpose via ldmatrix.trans
// (standard NS map 2X - T@X: self-corrects both symmetric and antisymmetric error).
// nchunks=16: 1-pass (Ah@Bh); nchunks=48: 3-pass (Ah@Bh + Ah@Bl + Al@Bh). Chunk = 32 K-cols.
#define NSA 5120                 // A tile: 64 rows x 80B
#define NSB 4608                 // B tile: 32 k-rows x 144B
#define NS_BUF (NSA + NSB)
__global__ __launch_bounds__(256) void gemm_ns(
    const __nv_bfloat16* __restrict__ Ahp, const __nv_bfloat16* __restrict__ Alp,
    const __nv_bfloat16* __restrict__ Bhp, const __nv_bfloat16* __restrict__ Blp,
    const float* __restrict__ E, float* __restrict__ C,
    __nv_bfloat16* __restrict__ Ch, __nv_bfloat16* __restrict__ Cl,
    int mode, int nchunks) {
    __shared__ char sm[2 * NS_BUF];
    size_t zo = (size_t)blockIdx.z * DD;
    const char* Ah8 = (const char*)(Ahp + zo);
    const char* Al8 = (const char*)(Alp + zo);
    const char* Bh8 = (const char*)(Bhp + zo);
    const char* Bl8 = (const char*)(Blp + zo);
    E += zo; C += zo; Ch += zo; Cl += zo;
    uint32_t smb = smem_u32(sm);
    int tid = threadIdx.x, lane = tid & 31, wid = tid >> 5;
    int warp_m = (wid & 1) * 32, warp_n = (wid >> 1) * 16;
    int i0 = blockIdx.x * 64, j0 = blockIdx.y * 64;
    int ar = tid >> 2, aseg = (tid & 3) * 16;   // A: 64 rows x 64B
    int br = tid >> 3, bseg = (tid & 7) * 16;   // B: 32 rows x 128B

    float d[2][2][4];
#pragma unroll
    for (int a = 0; a < 2; a++)
#pragma unroll
        for (int b = 0; b < 2; b++)
#pragma unroll
            for (int k = 0; k < 4; k++) d[a][b][k] = 0.f;

    uint4 ra, rb;
#define NS_LOAD(c) do { \
        int p = (c) >> 4; int kb = ((c) & 15) * 64; \
        const char* Asrc = (p == 2) ? Al8 : Ah8; \
        const char* Bsrc = (p == 1) ? Bl8 : Bh8; \
        ra = *(const uint4*)(Asrc + (size_t)(i0 + ar) * 1024 + kb + aseg); \
        rb = *(const uint4*)(Bsrc + (size_t)(((c) & 15) * 32 + br) * 1024 + j0 * 2 + bseg); \
    } while (0)
#define NS_STS(buf) do { \
        *(uint4*)(sm + (buf) * NS_BUF + ar * 80 + aseg) = ra; \
        *(uint4*)(sm + (buf) * NS_BUF + NSA + br * 144 + bseg) = rb; \
    } while (0)

    NS_LOAD(0); NS_STS(0);
    __syncthreads();
    for (int c = 0; c < nchunks; c++) {
        int cur = c & 1;
        if (c < nchunks - 1) NS_LOAD(c + 1);
        uint32_t baseA = smb + cur * NS_BUF;
        uint32_t baseB = baseA + NSA;
#pragma unroll
        for (int ks = 0; ks < 2; ks++) {
            uint32_t afr[2][4], bfr[2][2], r4[4];
#pragma unroll
            for (int mi = 0; mi < 2; mi++)
                ldm4(afr[mi], baseA + (warp_m + mi * 16 + (lane & 15)) * 80 + (lane >> 4) * 16 + ks * 32);
            {
                int rowB = ks * 16 + ((lane >> 3) & 1) * 8 + (lane & 7);
                int colB = warp_n + (lane >> 4) * 8;
                ldm4t(r4, baseB + rowB * 144 + colB * 2);
            }
            bfr[0][0] = r4[0]; bfr[0][1] = r4[1]; bfr[1][0] = r4[2]; bfr[1][1] = r4[3];
#pragma unroll
            for (int mi = 0; mi < 2; mi++)
#pragma unroll
                for (int ni = 0; ni < 2; ni++)
                    mma16816(d[mi][ni], afr[mi], bfr[ni]);
        }
        if (c < nchunks - 1) NS_STS(1 - cur);
        __syncthreads();
    }
#pragma unroll
    for (int mi = 0; mi < 2; mi++)
#pragma unroll
        for (int ni = 0; ni < 2; ni++) {
            int col = j0 + warp_n + ni * 8 + 2 * (lane & 3);
#pragma unroll
            for (int h = 0; h < 2; h++) {
                int row = i0 + warp_m + mi * 16 + h * 8 + (lane >> 2);
                size_t idx = (size_t)row * D + col;
                float v0 = d[mi][ni][2 * h], v1 = d[mi][ni][2 * h + 1];
                if (mode) {
                    float2 e = *(const float2*)&E[idx];
                    v0 = 2.f * e.x - v0; v1 = 2.f * e.y - v1;
                }
                *(float2*)&C[idx] = make_float2(v0, v1);
                unsigned int hh, ll;
                bf16split2(v0, v1, hh, ll);
                *(unsigned int*)&Ch[idx] = hh;
                *(unsigned int*)&Cl[idx] = ll;
            }
        }
#undef NS_LOAD
#undef NS_STS
}

// ---------------- K6: w_c = P_c m_c, b_c = m^T w ----------------
__global__ void k_wb(const float* __restrict__ P) {
    int c = blockIdx.x, i = threadIdx.x;
    const float* Pc = P + (size_t)c * DD;
    float w = 0.f;
    for (int j = 0; j < D; j++) w += Pc[j * D + i] * g_mean[c][j];
    g_w[c][i] = w;
    __shared__ float red[D];
    red[i] = w * g_mean[c][i];
    __syncthreads();
    for (int s = 256; s > 0; s >>= 1) {
        if (i < s) red[i] += red[i + s];
        __syncthreads();
    }
    if (i == 0) g_b[c] = red[0];
}

// ---------------- Q split fp32 -> bf16 hi/lo ----------------
__global__ void k_split(const float* __restrict__ S, __nv_bfloat16* __restrict__ H,
                        __nv_bfloat16* __restrict__ L) {
    int i = blockIdx.x * 256 + threadIdx.x;
    float4 v = ((const float4*)S)[i];
    uint2 hh, ll;
    bf16split2(v.x, v.y, hh.x, ll.x);
    bf16split2(v.z, v.w, hh.y, ll.y);
    ((uint2*)H)[i] = hh;
    ((uint2*)L)[i] = ll;
}

// ---------------- K7: main pass S[c][q] = q^T P_c q via mma.sync ----------------
#define MB_BUF 20480  // A: 128 x 80B (10240) + B: 128 x 80B
__global__ __launch_bounds__(256, 2) void k_main_mma(
    const float* __restrict__ Q,
    const __nv_bfloat16* __restrict__ Qh, const __nv_bfloat16* __restrict__ Ql,
    const __nv_bfloat16* __restrict__ Phg, const __nv_bfloat16* __restrict__ Plg) {
    extern __shared__ char sm[];
    __shared__ float sRow[128][2];
    int cls = blockIdx.y;
    const char* Ph8 = (const char*)(Phg + (size_t)cls * DD);
    const char* Pl8 = (const char*)(Plg + (size_t)cls * DD);
    const char* Qh8 = (const char*)Qh;
    const char* Ql8 = (const char*)Ql;
    uint32_t smb = smem_u32(sm);
    int tid = threadIdx.x, lane = tid & 31, wid = tid >> 5;
    int warp_m = (wid >> 1) * 32, warp_n = (wid & 1) * 64;
    int q0 = blockIdx.x * 128;
    int r0 = tid >> 2, cseg = (tid & 3) * 16;
    float accS[4] = {0.f, 0.f, 0.f, 0.f};
    uint4 ra0, ra1, rb0, rb1;

#define MB_LOAD(c, n0) do { \
        int p = (c) >> 4; int kb = ((c) & 15) * 64 + cseg; \
        const char* Asrc = (p == 2) ? Ql8 : Qh8; \
        const char* Bsrc = (p == 1) ? Pl8 : Ph8; \
        ra0 = *(const uint4*)(Asrc + (size_t)(q0 + r0) * 1024 + kb); \
        ra1 = *(const uint4*)(Asrc + (size_t)(q0 + 64 + r0) * 1024 + kb); \
        rb0 = *(const uint4*)(Bsrc + (size_t)((n0) + r0) * 1024 + kb); \
        rb1 = *(const uint4*)(Bsrc + (size_t)((n0) + 64 + r0) * 1024 + kb); \
    } while (0)
#define MB_STS(buf) do { \
        char* dA = sm + (buf) * MB_BUF + r0 * 80 + cseg; \
        *(uint4*)dA = ra0; *(uint4*)(dA + 64 * 80) = ra1; \
        char* dB = sm + (buf) * MB_BUF + 10240 + r0 * 80 + cseg; \
        *(uint4*)dB = rb0; *(uint4*)(dB + 64 * 80) = rb1; \
    } while (0)

    for (int nt = 0; nt < 4; nt++) {
        int n0 = nt * 128;
        float d[2][8][4];
#pragma unroll
        for (int a = 0; a < 2; a++)
#pragma unroll
            for (int b = 0; b < 8; b++)
#pragma unroll
                for (int k = 0; k < 4; k++) d[a][b][k] = 0.f;
        MB_LOAD(0, n0); MB_STS(0);
        __syncthreads();
        for (int c = 0; c < 48; c++) {
            int cur = c & 1;
            if (c < 47) MB_LOAD(c + 1, n0);
            uint32_t baseA = smb + cur * MB_BUF;
            uint32_t baseB = baseA + 10240;
#pragma unroll
            for (int ks = 0; ks < 2; ks++) {
                uint32_t afr[2][4], bfr[8][2], r4[4];
#pragma unroll
                for (int mi = 0; mi < 2; mi++)
                    ldm4(afr[mi], baseA + (warp_m + mi * 16 + (lane & 15)) * 80 + (lane >> 4) * 16 + ks * 32);
#pragma unroll
                for (int j = 0; j < 4; j++) {
                    ldm4(r4, baseB + (warp_n + j * 16 + ((lane >> 4) & 1) * 8 + (lane & 7)) * 80 + ((lane >> 3) & 1) * 16 + ks * 32);
                    bfr[2 * j][0] = r4[0]; bfr[2 * j][1] = r4[1];
                    bfr[2 * j + 1][0] = r4[2]; bfr[2 * j + 1][1] = r4[3];
                }
#pragma unroll
                for (int mi = 0; mi < 2; mi++)
#pragma unroll
                    for (int ni = 0; ni < 8; ni++)
                        mma16816(d[mi][ni], afr[mi], bfr[ni]);
            }
            if (c < 47) MB_STS(1 - cur);
            __syncthreads();
        }
#pragma unroll
        for (int mi = 0; mi < 2; mi++)
#pragma unroll
            for (int h = 0; h < 2; h++) {
                int row = q0 + warp_m + mi * 16 + h * 8 + (lane >> 2);
                float a = 0.f;
#pragma unroll
                for (int ni = 0; ni < 8; ni++) {
                    int col = n0 + warp_n + ni * 8 + 2 * (lane & 3);
                    float2 qv = *(const float2*)&Q[(size_t)row * D + col];
                    a += d[mi][ni][2 * h] * qv.x + d[mi][ni][2 * h + 1] * qv.y;
                }
                accS[mi * 2 + h] += a;
            }
    }
#pragma unroll
    for (int i = 0; i < 4; i++) {
        accS[i] += __shfl_xor_sync(0xffffffffu, accS[i], 1);
        accS[i] += __shfl_xor_sync(0xffffffffu, accS[i], 2);
    }
    if ((lane & 3) == 0) {
#pragma unroll
        for (int mi = 0; mi < 2; mi++)
#pragma unroll
            for (int h = 0; h < 2; h++)
                sRow[warp_m + mi * 16 + h * 8 + (lane >> 2)][wid & 1] = accS[mi * 2 + h];
    }
    __syncthreads();
    if (tid < 128) g_S[cls][q0 + tid] = sRow[tid][0] + sRow[tid][1];
#undef MB_LOAD
#undef MB_STS
}

// ---------------- K8: logits ----------------
__global__ void k_final(const float* __restrict__ Q, float* __restrict__ out, int nq) {
    int w = (blockIdx.x * blockDim.x + threadIdx.x) >> 5;
    int lane = threadIdx.x & 31;
    if (w >= nq) return;
    float qw0 = 0.f, qw1 = 0.f;
    for (int k = lane; k < D; k += 32) {
        float qk = Q[w * D + k];
        qw0 += qk * g_w[0][k];
        qw1 += qk * g_w[1][k];
    }
    for (int o = 16; o > 0; o >>= 1) {
        qw0 += __shfl_down_sync(0xffffffffu, qw0, o);
        qw1 += __shfl_down_sync(0xffffffffu, qw1, o);
    }
    if (lane == 0) {
        out[w * 2 + 0] = -(g_S[0][w] - 2.f * qw0 + g_b[0]);
        out[w * 2 + 1] = -(g_S[1][w] - 2.f * qw1 + g_b[1]);
    }
}

// ---------------- launch ----------------
extern "C" void kernel_launch(void* const* d_in, const int* in_sizes, int n_in,
                              void* d_out, int out_size) {
    const float*        SF   = (const float*)d_in[0];
    const unsigned int* labw = (const unsigned int*)d_in[1];
    const float*        Q    = (const float*)d_in[2];
    float*              out  = (float*)d_out;
    int nq = in_sizes[2] / D;  // 16384

    float *pA, *pX0, *pX1, *pT;
    __nv_bfloat16 *pQh, *pQl, *pAh, *pAl, *pTh, *pTl, *pXh0, *pXl0, *pXh1, *pXl1;
    cudaGetSymbolAddress((void**)&pA, g_A);
    cudaGetSymbolAddress((void**)&pX0, g_NS0);
    cudaGetSymbolAddress((void**)&pX1, g_NS1);
    cudaGetSymbolAddress((void**)&pT, g_T);
    cudaGetSymbolAddress((void**)&pQh, g_Qh);
    cudaGetSymbolAddress((void**)&pQl, g_Ql);
    cudaGetSymbolAddress((void**)&pAh, g_Ah);
    cudaGetSymbolAddress((void**)&pAl, g_Al);
    cudaGetSymbolAddress((void**)&pTh, g_Th);
    cudaGetSymbolAddress((void**)&pTl, g_Tl);
    cudaGetSymbolAddress((void**)&pXh0, g_X0h);
    cudaGetSymbolAddress((void**)&pXl0, g_X0l);
    cudaGetSymbolAddress((void**)&pXh1, g_X1h);
    cudaGetSymbolAddress((void**)&pXl1, g_X1l);
    cudaFuncSetAttribute(k_main_mma, cudaFuncAttributeMaxDynamicSharedMemorySize, 2 * MB_BUF);

    k_mask<<<1, NSUP>>>(labw);
    k_sums<<<dim3(4, 4), 128>>>(SF);
    k_means<<<2, D>>>();
    k_gram<<<dim3(16, 16), dim3(16, 16)>>>(SF);
    k_assemble<<<dim3(DD / 256, 2), 256>>>();

    dim3 gns(8, 8, 2);
    // spectral bound via 1-pass bf16 GEMMs: T = A@A, X1 = T@T, fro(X1)
    gemm_ns<<<gns, 256>>>(pAh, pAl, pAh, pAl, pT, pT, pTh, pTl, 0, 16);
    gemm_ns<<<gns, 256>>>(pTh, pTl, pTh, pTl, pT, pX1, pXh1, pXl1, 0, 16);
    k_fro4<<<dim3(DD / 256, 2), 256>>>(pX1);
    k_init<<<dim3(DD / 256, 2), 256>>>();

    float *X = pX0, *Xn = pX1;
    __nv_bfloat16 *Xh = pXh0, *Xl = pXl0, *Xnh = pXh1, *Xnl = pXl1;
    for (int it = 0; it < NIT_CHEAP + NIT_FULL; it++) {
        int nch = (it < NIT_CHEAP) ? 16 : 48;
        // T = X @ A (+ split of T)
        gemm_ns<<<gns, 256>>>(Xh, Xl, pAh, pAl, pT, pT, pTh, pTl, 0, nch);
        // Xn = 2X - T @ X (+ split of Xn)
        gemm_ns<<<gns, 256>>>(pTh, pTl, Xh, Xl, X, Xn, Xnh, Xnl, 1, nch);
        float* tf = X; X = Xn; Xn = tf;
        __nv_bfloat16* tb;
        tb = Xh; Xh = Xnh; Xnh = tb;
        tb = Xl; Xl = Xnl; Xnl = tb;
    }
    // X / Xh / Xl now hold P_c and its bf16 split

    k_wb<<<2, D>>>(X);
    k_split<<<(nq * D) / 1024, 256>>>(Q, pQh, pQl);
    k_main_mma<<<dim3(nq / 128, 2), 256, 2 * MB_BUF>>>(Q, pQh, pQl, Xh, Xl);
    k_final<<<(nq * 32 + 255) / 256, 256>>>(Q, out, nq);
}

// round 6
// speedup vs baseline: 2.7825x; 1.1673x over previous
#include <cuda_runtime.h>
#include <cuda_bf16.h>
#include <cstdint>

#define D    512
#define DD   (512 * 512)
#define NSUP 512
#define NQMAX 16384
#define NIT_CHEAP 7
#define NIT_FULL  2

// ---------------- device scratch ----------------
__device__ float g_mask[NSUP];
__device__ float g_cnt[2];
__device__ float g_csum[2][D];
__device__ float g_mall[D];
__device__ float g_mean[2][D];
__device__ float g_G[DD];
__device__ float g_G0[DD];
__device__ float g_A[2 * DD];
__device__ float g_NS0[2 * DD];
__device__ float g_NS1[2 * DD];
__device__ float g_T[2 * DD];
__device__ float g_fro[2];
__device__ float g_w[2][D];
__device__ float g_b[2];
__device__ float g_S[2][NQMAX];
__device__ __nv_bfloat16 g_Qh[NQMAX * D];
__device__ __nv_bfloat16 g_Ah[2 * DD];
__device__ __nv_bfloat16 g_Al[2 * DD];
__device__ __nv_bfloat16 g_Th[2 * DD];
__device__ __nv_bfloat16 g_Tl[2 * DD];
__device__ __nv_bfloat16 g_X0h[2 * DD];
__device__ __nv_bfloat16 g_X0l[2 * DD];
__device__ __nv_bfloat16 g_X1h[2 * DD];
__device__ __nv_bfloat16 g_X1l[2 * DD];

// ---------------- helpers ----------------
__device__ __forceinline__ uint32_t smem_u32(const void* p) {
    uint32_t a;
    asm("{ .reg .u64 t; cvta.to.shared.u64 t, %1; cvt.u32.u64 %0, t; }" : "=r"(a) : "l"(p));
    return a;
}
__device__ __forceinline__ void mma16816(float* d, const uint32_t* a, const uint32_t* b) {
    asm volatile(
        "mma.sync.aligned.m16n8k16.row.col.f32.bf16.bf16.f32 "
        "{%0,%1,%2,%3}, {%4,%5,%6,%7}, {%8,%9}, {%0,%1,%2,%3};"
        : "+f"(d[0]), "+f"(d[1]), "+f"(d[2]), "+f"(d[3])
        : "r"(a[0]), "r"(a[1]), "r"(a[2]), "r"(a[3]), "r"(b[0]), "r"(b[1]));
}
__device__ __forceinline__ void ldm4(uint32_t* r, uint32_t addr) {
    asm volatile("ldmatrix.sync.aligned.m8n8.x4.shared.b16 {%0,%1,%2,%3}, [%4];"
                 : "=r"(r[0]), "=r"(r[1]), "=r"(r[2]), "=r"(r[3]) : "r"(addr));
}
__device__ __forceinline__ void ldm4t(uint32_t* r, uint32_t addr) {
    asm volatile("ldmatrix.sync.aligned.m8n8.x4.trans.shared.b16 {%0,%1,%2,%3}, [%4];"
                 : "=r"(r[0]), "=r"(r[1]), "=r"(r[2]), "=r"(r[3]) : "r"(addr));
}
__device__ __forceinline__ void bf16split2(float v0, float v1, unsigned int& hh, unsigned int& ll) {
    __nv_bfloat16 h0 = __float2bfloat16(v0), h1 = __float2bfloat16(v1);
    __nv_bfloat16 l0 = __float2bfloat16(v0 - __bfloat162float(h0));
    __nv_bfloat16 l1 = __float2bfloat16(v1 - __bfloat162float(h1));
    hh = ((unsigned int)*(unsigned short*)&h0) | (((unsigned int)*(unsigned short*)&h1) << 16);
    ll = ((unsigned int)*(unsigned short*)&l0) | (((unsigned int)*(unsigned short*)&l1) << 16);
}

// ---------------- K0: label mask + count + zero accumulators ----------------
__global__ void k_mask(const unsigned int* __restrict__ labw) {
    __shared__ int oddOr;
    __shared__ float red[NSUP];
    int i = threadIdx.x;
    if (i == 0) oddOr = 0;
    __syncthreads();
    unsigned int w = labw[i];
    if ((i & 1) && w) atomicOr(&oddOr, 1);
    __syncthreads();
    unsigned int li = oddOr ? labw[i] : labw[2 * i];
    float mv = (li == 0) ? 1.f : 0.f;
    g_mask[i] = mv;
    g_csum[0][i] = 0.f;
    g_csum[1][i] = 0.f;
    g_mall[i] = 0.f;
    if (i < 2) g_fro[i] = 0.f;
    red[i] = mv;
    __syncthreads();
    for (int s = 256; s > 0; s >>= 1) {
        if (i < s) red[i] += red[i + s];
        __syncthreads();
    }
    if (i == 0) { g_cnt[0] = red[0]; g_cnt[1] = (float)NSUP - red[0]; }
}

// ---------------- K1: per-class sums (parallel, atomics) ----------------
__global__ void k_sums(const float* __restrict__ X) {
    __shared__ float m[128];
    int t = threadIdx.x;  // 128
    int rb = blockIdx.y * 128;
    m[t] = g_mask[rb + t];
    __syncthreads();
    int j = blockIdx.x * 128 + t;
    float sa = 0.f, s0 = 0.f;
    for (int r = 0; r < 128; r++) {
        float x = X[(size_t)(rb + r) * D + j];
        sa += x; s0 += m[r] * x;
    }
    atomicAdd(&g_mall[j], sa);
    atomicAdd(&g_csum[0][j], s0);
    atomicAdd(&g_csum[1][j], sa - s0);
}

__global__ void k_means() {
    int c = blockIdx.x, j = threadIdx.x;
    if (c == 0) g_mall[j] *= (1.f / (float)NSUP);
    g_mean[c][j] = g_csum[c][j] / g_cnt[c];
}

// ---------------- K3: Gram matrices (lower-triangle blocks only, mirrored) ----------------
__global__ void k_gram(const float* __restrict__ X) {
    __shared__ float As[16][33], Bs[16][33], Ms[16];
    int tx = threadIdx.x, ty = threadIdx.y;
    int t = ty * 16 + tx;
    // map linear block -> (bi, bj) with bi <= bj over 16x16 block grid
    int b = blockIdx.x, bi = 0;
    while (b >= 16 - bi) { b -= 16 - bi; bi++; }
    int bj = bi + b;
    int i0 = bi * 32, j0 = bj * 32;
    float aA[2][2] = {}, a0[2][2] = {};
    int rr = t >> 4, cc = (t & 15) * 2;
    for (int r0 = 0; r0 < NSUP; r0 += 16) {
        float2 av = *(const float2*)&X[(r0 + rr) * D + i0 + cc];
        As[rr][cc] = av.x; As[rr][cc + 1] = av.y;
        float2 bv = *(const float2*)&X[(r0 + rr) * D + j0 + cc];
        Bs[rr][cc] = bv.x; Bs[rr][cc + 1] = bv.y;
        if (t < 16) Ms[t] = g_mask[r0 + t];
        __syncthreads();
#pragma unroll
        for (int k = 0; k < 16; k++) {
            float mm = Ms[k];
            float ax = As[k][ty * 2], ay = As[k][ty * 2 + 1];
            float bx = Bs[k][tx * 2], by = Bs[k][tx * 2 + 1];
            float p;
            p = ax * bx; aA[0][0] += p; a0[0][0] += mm * p;
            p = ax * by; aA[0][1] += p; a0[0][1] += mm * p;
            p = ay * bx; aA[1][0] += p; a0[1][0] += mm * p;
            p = ay * by; aA[1][1] += p; a0[1][1] += mm * p;
        }
        __syncthreads();
    }
#pragma unroll
    for (int i = 0; i < 2; i++)
#pragma unroll
        for (int j = 0; j < 2; j++) {
            int gi = i0 + ty * 2 + i, gj = j0 + tx * 2 + j;
            g_G[gi * D + gj] = aA[i][j];
            g_G0[gi * D + gj] = a0[i][j];
            g_G[gj * D + gi] = aA[i][j];
            g_G0[gj * D + gi] = a0[i][j];
        }
}

// ---------------- K4: assemble A_c (+ bf16 split) ----------------
__global__ void k_assemble() {
    int c = blockIdx.y;
    int t = blockIdx.x * 256 + threadIdx.x;
    int i = t >> 9, j = t & (D - 1);
    float g = g_G[t], g0 = g_G0[t];
    float gc = c ? (g - g0) : g0;
    float nc = g_cnt[c];
    float covc = (gc - nc * g_mean[c][i] * g_mean[c][j]) / (nc - 1.f);
    float task = (g - (float)NSUP * g_mall[i] * g_mall[j]) / ((float)NSUP - 1.f);
    float lam = fminf(nc / (nc + 1.f), 0.1f);
    float a = lam * covc + (1.f - lam) * task + ((i == j) ? 0.1f : 0.f);
    int idx = c * DD + t;
    g_A[idx] = a;
    __nv_bfloat16 h = __float2bfloat16(a);
    g_Ah[idx] = h;
    g_Al[idx] = __float2bfloat16(a - __bfloat162float(h));
}

// ---------------- K4b: Frobenius^2 of A^4 ----------------
__global__ void k_fro4(const float* __restrict__ M4) {
    int c = blockIdx.y;
    int t = blockIdx.x * 256 + threadIdx.x;
    float a = M4[(size_t)c * DD + t];
    __shared__ float red[256];
    red[threadIdx.x] = a * a;
    __syncthreads();
    for (int s = 128; s > 0; s >>= 1) {
        if (threadIdx.x < s) red[threadIdx.x] += red[threadIdx.x + s];
        __syncthreads();
    }
    if (threadIdx.x == 0) atomicAdd(&g_fro[c], red[0]);
}

// ---------------- K5: NS init X0 = alpha*I (+ split) ----------------
__global__ void k_init() {
    int c = blockIdx.y;
    int t = blockIdx.x * 256 + threadIdx.x;
    int i = t >> 9, j = t & (D - 1);
    float lub = 1.02f * powf(g_fro[c], 0.125f) + 0.02f;  // safe upper bound on lambda_max
    float alpha = 2.f / (lub + 0.1f);
    float v = (i == j) ? alpha : 0.f;
    int idx = c * DD + t;
    g_NS0[idx] = v;
    __nv_bfloat16 h = __float2bfloat16(v);
    g_X0h[idx] = h;
    g_X0l[idx] = __float2bfloat16(v - __bfloat162float(h));
}

// ---------------- NS GEMM: C = A@B (mode0) or 2E - A@B (mode1), + bf16 split out ----------------
#define NSA 5120                 // A tile: 64 rows x 80B
#define NSB 4608                 // B tile: 32 k-rows x 144B
#define NS_BUF (NSA + NSB)
__global__ __launch_bounds__(256) void gemm_ns(
    const __nv_bfloat16* __restrict__ Ahp, const __nv_bfloat16* __restrict__ Alp,
    const __nv_bfloat16* __restrict__ Bhp, const __nv_bfloat16* __restrict__ Blp,
    const float* __restrict__ E, float* __restrict__ C,
    __nv_bfloat16* __restrict__ Ch, __nv_bfloat16* __restrict__ Cl,
    int mode, int nchunks) {
    __shared__ char sm[2 * NS_BUF];
    size_t zo = (size_t)blockIdx.z * DD;
    const char* Ah8 = (const char*)(Ahp + zo);
    const char* Al8 = (const char*)(Alp + zo);
    const char* Bh8 = (const char*)(Bhp + zo);
    const char* Bl8 = (const char*)(Blp + zo);
    E += zo; C += zo; Ch += zo; Cl += zo;
    uint32_t smb = smem_u32(sm);
    int tid = threadIdx.x, lane = tid & 31, wid = tid >> 5;
    int warp_m = (wid & 1) * 32, warp_n = (wid >> 1) * 16;
    int i0 = blockIdx.x * 64, j0 = blockIdx.y * 64;
    int ar = tid >> 2, aseg = (tid & 3) * 16;
    int br = tid >> 3, bseg = (tid & 7) * 16;

    float d[2][2][4];
#pragma unroll
    for (int a = 0; a < 2; a++)
#pragma unroll
        for (int b = 0; b < 2; b++)
#pragma unroll
            for (int k = 0; k < 4; k++) d[a][b][k] = 0.f;

    uint4 ra, rb;
#define NS_LOAD(c) do { \
        int p = (c) >> 4; int kb = ((c) & 15) * 64; \
        const char* Asrc = (p == 2) ? Al8 : Ah8; \
        const char* Bsrc = (p == 1) ? Bl8 : Bh8; \
        ra = *(const uint4*)(Asrc + (size_t)(i0 + ar) * 1024 + kb + aseg); \
        rb = *(const uint4*)(Bsrc + (size_t)(((c) & 15) * 32 + br) * 1024 + j0 * 2 + bseg); \
    } while (0)
#define NS_STS(buf) do { \
        *(uint4*)(sm + (buf) * NS_BUF + ar * 80 + aseg) = ra; \
        *(uint4*)(sm + (buf) * NS_BUF + NSA + br * 144 + bseg) = rb; \
    } while (0)

    NS_LOAD(0); NS_STS(0);
    __syncthreads();
    for (int c = 0; c < nchunks; c++) {
        int cur = c & 1;
        if (c < nchunks - 1) NS_LOAD(c + 1);
        uint32_t baseA = smb + cur * NS_BUF;
        uint32_t baseB = baseA + NSA;
#pragma unroll
        for (int ks = 0; ks < 2; ks++) {
            uint32_t afr[2][4], bfr[2][2], r4[4];
#pragma unroll
            for (int mi = 0; mi < 2; mi++)
                ldm4(afr[mi], baseA + (warp_m + mi * 16 + (lane & 15)) * 80 + (lane >> 4) * 16 + ks * 32);
            {
                int rowB = ks * 16 + ((lane >> 3) & 1) * 8 + (lane & 7);
                int colB = warp_n + (lane >> 4) * 8;
                ldm4t(r4, baseB + rowB * 144 + colB * 2);
            }
            bfr[0][0] = r4[0]; bfr[0][1] = r4[1]; bfr[1][0] = r4[2]; bfr[1][1] = r4[3];
#pragma unroll
            for (int mi = 0; mi < 2; mi++)
#pragma unroll
                for (int ni = 0; ni < 2; ni++)
                    mma16816(d[mi][ni], afr[mi], bfr[ni]);
        }
        if (c < nchunks - 1) NS_STS(1 - cur);
        __syncthreads();
    }
#pragma unroll
    for (int mi = 0; mi < 2; mi++)
#pragma unroll
        for (int ni = 0; ni < 2; ni++) {
            int col = j0 + warp_n + ni * 8 + 2 * (lane & 3);
#pragma unroll
            for (int h = 0; h < 2; h++) {
                int row = i0 + warp_m + mi * 16 + h * 8 + (lane >> 2);
                size_t idx = (size_t)row * D + col;
                float v0 = d[mi][ni][2 * h], v1 = d[mi][ni][2 * h + 1];
                if (mode) {
                    float2 e = *(const float2*)&E[idx];
                    v0 = 2.f * e.x - v0; v1 = 2.f * e.y - v1;
                }
                *(float2*)&C[idx] = make_float2(v0, v1);
                unsigned int hh, ll;
                bf16split2(v0, v1, hh, ll);
                *(unsigned int*)&Ch[idx] = hh;
                *(unsigned int*)&Cl[idx] = ll;
            }
        }
#undef NS_LOAD
#undef NS_STS
}

// ---------------- K6: w_c = P_c m_c, b_c = m^T w ----------------
__global__ void k_wb(const float* __restrict__ P) {
    int c = blockIdx.x, i = threadIdx.x;
    const float* Pc = P + (size_t)c * DD;
    float w = 0.f;
    for (int j = 0; j < D; j++) w += Pc[j * D + i] * g_mean[c][j];
    g_w[c][i] = w;
    __shared__ float red[D];
    red[i] = w * g_mean[c][i];
    __syncthreads();
    for (int s = 256; s > 0; s >>= 1) {
        if (i < s) red[i] += red[i + s];
        __syncthreads();
    }
    if (i == 0) g_b[c] = red[0];
}

// ---------------- Q split fp32 -> bf16 hi only ----------------
__global__ void k_split(const float* __restrict__ S, __nv_bfloat16* __restrict__ H) {
    int i = blockIdx.x * 256 + threadIdx.x;
    float4 v = ((const float4*)S)[i];
    __nv_bfloat16 h0 = __float2bfloat16(v.x), h1 = __float2bfloat16(v.y);
    __nv_bfloat16 h2 = __float2bfloat16(v.z), h3 = __float2bfloat16(v.w);
    uint2 hh;
    hh.x = ((unsigned int)*(unsigned short*)&h0) | (((unsigned int)*(unsigned short*)&h1) << 16);
    hh.y = ((unsigned int)*(unsigned short*)&h2) | (((unsigned int)*(unsigned short*)&h3) << 16);
    ((uint2*)H)[i] = hh;
}

// ---------------- K7: main pass, 2-pass: H = Qh@(Ph+Pl); S = H . (2q - qh) ----------------
#define MB_BUF 20480  // A: 128 x 80B (10240) + B: 128 x 80B
__global__ __launch_bounds__(256, 2) void k_main_mma(
    const float* __restrict__ Q,
    const __nv_bfloat16* __restrict__ Qh,
    const __nv_bfloat16* __restrict__ Phg, const __nv_bfloat16* __restrict__ Plg) {
    extern __shared__ char sm[];
    __shared__ float sRow[128][2];
    int cls = blockIdx.y;
    const char* Ph8 = (const char*)(Phg + (size_t)cls * DD);
    const char* Pl8 = (const char*)(Plg + (size_t)cls * DD);
    const char* Qh8 = (const char*)Qh;
    uint32_t smb = smem_u32(sm);
    int tid = threadIdx.x, lane = tid & 31, wid = tid >> 5;
    int warp_m = (wid >> 1) * 32, warp_n = (wid & 1) * 64;
    int q0 = blockIdx.x * 128;
    int r0 = tid >> 2, cseg = (tid & 3) * 16;
    float accS[4] = {0.f, 0.f, 0.f, 0.f};
    uint4 ra0, ra1, rb0, rb1;

#define MB_LOAD(c, n0) do { \
        int p = (c) >> 4; int kb = ((c) & 15) * 64 + cseg; \
        const char* Bsrc = p ? Pl8 : Ph8; \
        ra0 = *(const uint4*)(Qh8 + (size_t)(q0 + r0) * 1024 + kb); \
        ra1 = *(const uint4*)(Qh8 + (size_t)(q0 + 64 + r0) * 1024 + kb); \
        rb0 = *(const uint4*)(Bsrc + (size_t)((n0) + r0) * 1024 + kb); \
        rb1 = *(const uint4*)(Bsrc + (size_t)((n0) + 64 + r0) * 1024 + kb); \
    } while (0)
#define MB_STS(buf) do { \
        char* dA = sm + (buf) * MB_BUF + r0 * 80 + cseg; \
        *(uint4*)dA = ra0; *(uint4*)(dA + 64 * 80) = ra1; \
        char* dB = sm + (buf) * MB_BUF + 10240 + r0 * 80 + cseg; \
        *(uint4*)dB = rb0; *(uint4*)(dB + 64 * 80) = rb1; \
    } while (0)

    for (int nt = 0; nt < 4; nt++) {
        int n0 = nt * 128;
        float d[2][8][4];
#pragma unroll
        for (int a = 0; a < 2; a++)
#pragma unroll
            for (int b = 0; b < 8; b++)
#pragma unroll
                for (int k = 0; k < 4; k++) d[a][b][k] = 0.f;
        MB_LOAD(0, n0); MB_STS(0);
        __syncthreads();
        for (int c = 0; c < 32; c++) {
            int cur = c & 1;
            if (c < 31) MB_LOAD(c + 1, n0);
            uint32_t baseA = smb + cur * MB_BUF;
            uint32_t baseB = baseA + 10240;
#pragma unroll
            for (int ks = 0; ks < 2; ks++) {
                uint32_t afr[2][4], bfr[8][2], r4[4];
#pragma unroll
                for (int mi = 0; mi < 2; mi++)
                    ldm4(afr[mi], baseA + (warp_m + mi * 16 + (lane & 15)) * 80 + (lane >> 4) * 16 + ks * 32);
#pragma unroll
                for (int j = 0; j < 4; j++) {
                    ldm4(r4, baseB + (warp_n + j * 16 + ((lane >> 4) & 1) * 8 + (lane & 7)) * 80 + ((lane >> 3) & 1) * 16 + ks * 32);
                    bfr[2 * j][0] = r4[0]; bfr[2 * j][1] = r4[1];
                    bfr[2 * j + 1][0] = r4[2]; bfr[2 * j + 1][1] = r4[3];
                }
#pragma unroll
                for (int mi = 0; mi < 2; mi++)
#pragma unroll
                    for (int ni = 0; ni < 8; ni++)
                        mma16816(d[mi][ni], afr[mi], bfr[ni]);
            }
            if (c < 31) MB_STS(1 - cur);
            __syncthreads();
        }
        // fused dot with v = 2q - qh  (recovers the Ql@Ph pass via symmetry of P)
#pragma unroll
        for (int mi = 0; mi < 2; mi++)
#pragma unroll
            for (int h = 0; h < 2; h++) {
                int row = q0 + warp_m + mi * 16 + h * 8 + (lane >> 2);
                float a = 0.f;
#pragma unroll
                for (int ni = 0; ni < 8; ni++) {
                    int col = n0 + warp_n + ni * 8 + 2 * (lane & 3);
                    float2 qv = *(const float2*)&Q[(size_t)row * D + col];
                    unsigned int qh2 = *(const unsigned int*)&Qh[(size_t)row * D + col];
                    __nv_bfloat16 h0 = *(__nv_bfloat16*)&qh2;
                    unsigned short u1 = (unsigned short)(qh2 >> 16);
                    __nv_bfloat16 h1 = *(__nv_bfloat16*)&u1;
                    float v0 = 2.f * qv.x - __bfloat162float(h0);
                    float v1 = 2.f * qv.y - __bfloat162float(h1);
                    a += d[mi][ni][2 * h] * v0 + d[mi][ni][2 * h + 1] * v1;
                }
                accS[mi * 2 + h] += a;
            }
    }
#pragma unroll
    for (int i = 0; i < 4; i++) {
        accS[i] += __shfl_xor_sync(0xffffffffu, accS[i], 1);
        accS[i] += __shfl_xor_sync(0xffffffffu, accS[i], 2);
    }
    if ((lane & 3) == 0) {
#pragma unroll
        for (int mi = 0; mi < 2; mi++)
#pragma unroll
            for (int h = 0; h < 2; h++)
                sRow[warp_m + mi * 16 + h * 8 + (lane >> 2)][wid & 1] = accS[mi * 2 + h];
    }
    __syncthreads();
    if (tid < 128) g_S[cls][q0 + tid] = sRow[tid][0] + sRow[tid][1];
#undef MB_LOAD
#undef MB_STS
}

// ---------------- K8: logits ----------------
__global__ void k_final(const float* __restrict__ Q, float* __restrict__ out, int nq) {
    int w = (blockIdx.x * blockDim.x + threadIdx.x) >> 5;
    int lane = threadIdx.x & 31;
    if (w >= nq) return;
    float qw0 = 0.f, qw1 = 0.f;
    for (int k = lane; k < D; k += 32) {
        float qk = Q[w * D + k];
        qw0 += qk * g_w[0][k];
        qw1 += qk * g_w[1][k];
    }
    for (int o = 16; o > 0; o >>= 1) {
        qw0 += __shfl_down_sync(0xffffffffu, qw0, o);
        qw1 += __shfl_down_sync(0xffffffffu, qw1, o);
    }
    if (lane == 0) {
        out[w * 2 + 0] = -(g_S[0][w] - 2.f * qw0 + g_b[0]);
        out[w * 2 + 1] = -(g_S[1][w] - 2.f * qw1 + g_b[1]);
    }
}

// ---------------- launch ----------------
extern "C" void kernel_launch(void* const* d_in, const int* in_sizes, int n_in,
                              void* d_out, int out_size) {
    const float*        SF   = (const float*)d_in[0];
    const unsigned int* labw = (const unsigned int*)d_in[1];
    const float*        Q    = (const float*)d_in[2];
    float*              out  = (float*)d_out;
    int nq = in_sizes[2] / D;  // 16384

    float *pA, *pX0, *pX1, *pT;
    __nv_bfloat16 *pQh, *pAh, *pAl, *pTh, *pTl, *pXh0, *pXl0, *pXh1, *pXl1;
    cudaGetSymbolAddress((void**)&pA, g_A);
    cudaGetSymbolAddress((void**)&pX0, g_NS0);
    cudaGetSymbolAddress((void**)&pX1, g_NS1);
    cudaGetSymbolAddress((void**)&pT, g_T);
    cudaGetSymbolAddress((void**)&pQh, g_Qh);
    cudaGetSymbolAddress((void**)&pAh, g_Ah);
    cudaGetSymbolAddress((void**)&pAl, g_Al);
    cudaGetSymbolAddress((void**)&pTh, g_Th);
    cudaGetSymbolAddress((void**)&pTl, g_Tl);
    cudaGetSymbolAddress((void**)&pXh0, g_X0h);
    cudaGetSymbolAddress((void**)&pXl0, g_X0l);
    cudaGetSymbolAddress((void**)&pXh1, g_X1h);
    cudaGetSymbolAddress((void**)&pXl1, g_X1l);
    cudaFuncSetAttribute(k_main_mma, cudaFuncAttributeMaxDynamicSharedMemorySize, 2 * MB_BUF);

    k_mask<<<1, NSUP>>>(labw);
    k_sums<<<dim3(4, 4), 128>>>(SF);
    k_means<<<2, D>>>();
    k_gram<<<136, dim3(16, 16)>>>(SF);
    k_assemble<<<dim3(DD / 256, 2), 256>>>();

    dim3 gns(8, 8, 2);
    // spectral bound via 1-pass bf16 GEMMs: T = A@A, X1 = T@T, fro(X1)
    gemm_ns<<<gns, 256>>>(pAh, pAl, pAh, pAl, pT, pT, pTh, pTl, 0, 16);
    gemm_ns<<<gns, 256>>>(pTh, pTl, pTh, pTl, pT, pX1, pXh1, pXl1, 0, 16);
    k_fro4<<<dim3(DD / 256, 2), 256>>>(pX1);
    k_init<<<dim3(DD / 256, 2), 256>>>();

    float *X = pX0, *Xn = pX1;
    __nv_bfloat16 *Xh = pXh0, *Xl = pXl0, *Xnh = pXh1, *Xnl = pXl1;
    for (int it = 0; it < NIT_CHEAP + NIT_FULL; it++) {
        int nch = (it < NIT_CHEAP) ? 16 : 48;
        gemm_ns<<<gns, 256>>>(Xh, Xl, pAh, pAl, pT, pT, pTh, pTl, 0, nch);
        gemm_ns<<<gns, 256>>>(pTh, pTl, Xh, Xl, X, Xn, Xnh, Xnl, 1, nch);
        float* tf = X; X = Xn; Xn = tf;
        __nv_bfloat16* tb;
        tb = Xh; Xh = Xnh; Xnh = tb;
        tb = Xl; Xl = Xnl; Xnl = tb;
    }
    // X / Xh / Xl now hold P_c and its bf16 split

    k_wb<<<2, D>>>(X);
    k_split<<<(nq * D) / 1024, 256>>>(Q, pQh);
    k_main_mma<<<dim3(nq / 128, 2), 256, 2 * MB_BUF>>>(Q, pQh, Xh, Xl);
    k_final<<<(nq * 32 + 255) / 256, 256>>>(Q, out, nq);
}

// round 8
// speedup vs baseline: 3.2541x; 1.1695x over previous
#include <cuda_runtime.h>
#include <cuda_bf16.h>
#include <cstdint>

#define D    512
#define DD   (512 * 512)
#define NSUP 512
#define NQMAX 16384
#define NIT_CHEAP 5
#define NIT_FULL  2

// ---------------- device scratch ----------------
__device__ float g_mask[NSUP];
__device__ float g_cnt[2];
__device__ float g_csum[2][D];
__device__ float g_mall[D];
__device__ float g_mean[2][D];
__device__ float g_G[DD];        // U = Xh^T Xh
__device__ float g_G0[DD];       // W = Xh^T Xl
__device__ float g_A[2 * DD];
__device__ float g_NS0[2 * DD];  // first: U0/W0 during stats; later X ping-pong
__device__ float g_NS1[2 * DD];
__device__ float g_T[2 * DD];    // V/V0 during stats; later NS temp
__device__ float g_fro[2];
__device__ float g_w[2][D];
__device__ float g_b[2];
__device__ float g_S[2][NQMAX];
__device__ __nv_bfloat16 g_Qh[NQMAX * D];
__device__ __nv_bfloat16 g_Ah[2 * DD];
__device__ __nv_bfloat16 g_Al[2 * DD];
__device__ __nv_bfloat16 g_Th[2 * DD];   // support split Xh lives here pre-spectral
__device__ __nv_bfloat16 g_Tl[2 * DD];
__device__ __nv_bfloat16 g_X0h[2 * DD];
__device__ __nv_bfloat16 g_X0l[2 * DD];
__device__ __nv_bfloat16 g_X1h[2 * DD];
__device__ __nv_bfloat16 g_X1l[2 * DD];

// ---------------- helpers ----------------
__device__ __forceinline__ uint32_t smem_u32(const void* p) {
    uint32_t a;
    asm("{ .reg .u64 t; cvta.to.shared.u64 t, %1; cvt.u32.u64 %0, t; }" : "=r"(a) : "l"(p));
    return a;
}
__device__ __forceinline__ void mma16816(float* d, const uint32_t* a, const uint32_t* b) {
    asm volatile(
        "mma.sync.aligned.m16n8k16.row.col.f32.bf16.bf16.f32 "
        "{%0,%1,%2,%3}, {%4,%5,%6,%7}, {%8,%9}, {%0,%1,%2,%3};"
        : "+f"(d[0]), "+f"(d[1]), "+f"(d[2]), "+f"(d[3])
        : "r"(a[0]), "r"(a[1]), "r"(a[2]), "r"(a[3]), "r"(b[0]), "r"(b[1]));
}
__device__ __forceinline__ void ldm4(uint32_t* r, uint32_t addr) {
    asm volatile("ldmatrix.sync.aligned.m8n8.x4.shared.b16 {%0,%1,%2,%3}, [%4];"
                 : "=r"(r[0]), "=r"(r[1]), "=r"(r[2]), "=r"(r[3]) : "r"(addr));
}
__device__ __forceinline__ void ldm4t(uint32_t* r, uint32_t addr) {
    asm volatile("ldmatrix.sync.aligned.m8n8.x4.trans.shared.b16 {%0,%1,%2,%3}, [%4];"
                 : "=r"(r[0]), "=r"(r[1]), "=r"(r[2]), "=r"(r[3]) : "r"(addr));
}
__device__ __forceinline__ void bf16split2(float v0, float v1, unsigned int& hh, unsigned int& ll) {
    __nv_bfloat16 h0 = __float2bfloat16(v0), h1 = __float2bfloat16(v1);
    __nv_bfloat16 l0 = __float2bfloat16(v0 - __bfloat162float(h0));
    __nv_bfloat16 l1 = __float2bfloat16(v1 - __bfloat162float(h1));
    hh = ((unsigned int)*(unsigned short*)&h0) | (((unsigned int)*(unsigned short*)&h1) << 16);
    ll = ((unsigned int)*(unsigned short*)&l0) | (((unsigned int)*(unsigned short*)&l1) << 16);
}

// ---------------- K0: label mask + count + zero accumulators ----------------
__global__ void k_mask(const unsigned int* __restrict__ labw) {
    __shared__ int oddOr;
    __shared__ float red[NSUP];
    int i = threadIdx.x;
    if (i == 0) oddOr = 0;
    __syncthreads();
    unsigned int w = labw[i];
    if ((i & 1) && w) atomicOr(&oddOr, 1);
    __syncthreads();
    unsigned int li = oddOr ? labw[i] : labw[2 * i];
    float mv = (li == 0) ? 1.f : 0.f;
    g_mask[i] = mv;
    g_csum[0][i] = 0.f;
    g_csum[1][i] = 0.f;
    g_mall[i] = 0.f;
    if (i < 2) { g_fro[i] = 0.f; g_b[i] = 0.f; }
    red[i] = mv;
    __syncthreads();
    for (int s = 256; s > 0; s >>= 1) {
        if (i < s) red[i] += red[i + s];
        __syncthreads();
    }
    if (i == 0) { g_cnt[0] = red[0]; g_cnt[1] = (float)NSUP - red[0]; }
}

// ---------------- K1: per-class sums (parallel, atomics) ----------------
__global__ void k_sums(const float* __restrict__ X) {
    __shared__ float m[128];
    int t = threadIdx.x;
    int rb = blockIdx.y * 128;
    m[t] = g_mask[rb + t];
    __syncthreads();
    int j = blockIdx.x * 128 + t;
    float sa = 0.f, s0 = 0.f;
    for (int r = 0; r < 128; r++) {
        float x = X[(size_t)(rb + r) * D + j];
        sa += x; s0 += m[r] * x;
    }
    atomicAdd(&g_mall[j], sa);
    atomicAdd(&g_csum[0][j], s0);
    atomicAdd(&g_csum[1][j], sa - s0);
}

__global__ void k_means() {
    int c = blockIdx.x, j = threadIdx.x;
    if (c == 0) g_mall[j] *= (1.f / (float)NSUP);
    g_mean[c][j] = g_csum[c][j] / g_cnt[c];
}

// ---------------- split fp32 -> bf16 hi+lo ----------------
__global__ void k_split2(const float* __restrict__ S, __nv_bfloat16* __restrict__ H,
                         __nv_bfloat16* __restrict__ L) {
    int i = blockIdx.x * 256 + threadIdx.x;
    float4 v = ((const float4*)S)[i];
    uint2 hh, ll;
    bf16split2(v.x, v.y, hh.x, ll.x);
    bf16split2(v.z, v.w, hh.y, ll.y);
    ((uint2*)H)[i] = hh;
    ((uint2*)L)[i] = ll;
}

// ---------------- K3: Gram via tensor cores ----------------
// U=Xh^T Xh, W=Xh^T Xl, V=Xl^T Xl, U0=Mh^T Xh, W0=Mh^T Xl, V0=Ml^T Xl
// G = U + W + W^T + V ; G0 = U0 + W0 + W0^T + V0  (assembled in k_assemble)
#define GTP 144
#define GTT 4608  // 32 rows x 144B
__global__ __launch_bounds__(256) void k_gram_tc(
    const __nv_bfloat16* __restrict__ Xh, const __nv_bfloat16* __restrict__ Xl,
    float* __restrict__ U, float* __restrict__ W, float* __restrict__ V,
    float* __restrict__ U0, float* __restrict__ W0, float* __restrict__ V0) {
    __shared__ char sm[6 * GTT];
    uint32_t smb = smem_u32(sm);
    const char* Xh8 = (const char*)Xh;
    const char* Xl8 = (const char*)Xl;
    int tid = threadIdx.x, lane = tid & 31, wid = tid >> 5;
    int warp_m = (wid & 3) * 16, warp_n = (wid >> 2) * 32;
    int i0 = blockIdx.x * 64, j0 = blockIdx.y * 64;
    int row = tid >> 3, seg = (tid & 7) * 16;
    float d[6][4][4];
#pragma unroll
    for (int p = 0; p < 6; p++)
#pragma unroll
        for (int n = 0; n < 4; n++)
#pragma unroll
            for (int k = 0; k < 4; k++) d[p][n][k] = 0.f;

    for (int ch = 0; ch < 16; ch++) {
        int r0 = ch * 32;
        float mr = g_mask[r0 + row];
        size_t ro = (size_t)(r0 + row) * 1024;
        uint4 hi = *(const uint4*)(Xh8 + ro + i0 * 2 + seg);
        uint4 li = *(const uint4*)(Xl8 + ro + i0 * 2 + seg);
        uint4 hj = *(const uint4*)(Xh8 + ro + j0 * 2 + seg);
        uint4 lj = *(const uint4*)(Xl8 + ro + j0 * 2 + seg);
        uint4 zz = make_uint4(0u, 0u, 0u, 0u);
        uint4 mhi = (mr > 0.5f) ? hi : zz;
        uint4 mli = (mr > 0.5f) ? li : zz;
        __syncthreads();
        char* base = sm + row * GTP + seg;
        *(uint4*)(base + 0 * GTT) = hi;
        *(uint4*)(base + 1 * GTT) = li;
        *(uint4*)(base + 2 * GTT) = mhi;
        *(uint4*)(base + 3 * GTT) = mli;
        *(uint4*)(base + 4 * GTT) = hj;
        *(uint4*)(base + 5 * GTT) = lj;
        __syncthreads();
#pragma unroll
        for (int ks = 0; ks < 2; ks++) {
            uint32_t fa[4][4];
            uint32_t arow = (uint32_t)(ks * 16 + (lane >> 4) * 8 + (lane & 7)) * GTP
                          + (warp_m + ((lane >> 3) & 1) * 8) * 2;
#pragma unroll
            for (int p = 0; p < 4; p++) ldm4t(fa[p], smb + p * GTT + arow);
            uint32_t fb[2][4][2];
#pragma unroll
            for (int bm = 0; bm < 2; bm++)
#pragma unroll
                for (int nn = 0; nn < 2; nn++) {
                    uint32_t r4[4];
                    uint32_t baddr = smb + (4 + bm) * GTT
                        + (uint32_t)(ks * 16 + ((lane >> 3) & 1) * 8 + (lane & 7)) * GTP
                        + (warp_n + nn * 16 + (lane >> 4) * 8) * 2;
                    ldm4t(r4, baddr);
                    fb[bm][nn * 2][0] = r4[0]; fb[bm][nn * 2][1] = r4[1];
                    fb[bm][nn * 2 + 1][0] = r4[2]; fb[bm][nn * 2 + 1][1] = r4[3];
                }
#pragma unroll
            for (int ni = 0; ni < 4; ni++) {
                mma16816(d[0][ni], fa[0], fb[0][ni]);  // U
                mma16816(d[1][ni], fa[0], fb[1][ni]);  // W
                mma16816(d[2][ni], fa[1], fb[1][ni]);  // V
                mma16816(d[3][ni], fa[2], fb[0][ni]);  // U0
                mma16816(d[4][ni], fa[2], fb[1][ni]);  // W0
                mma16816(d[5][ni], fa[3], fb[1][ni]);  // V0
            }
        }
    }
    float* outs[6] = {U, W, V, U0, W0, V0};
#pragma unroll
    for (int p = 0; p < 6; p++)
#pragma unroll
        for (int ni = 0; ni < 4; ni++) {
            int col = j0 + warp_n + ni * 8 + 2 * (lane & 3);
#pragma unroll
            for (int h = 0; h < 2; h++) {
                int r = i0 + warp_m + h * 8 + (lane >> 2);
                *(float2*)&outs[p][(size_t)r * D + col] =
                    make_float2(d[p][ni][2 * h], d[p][ni][2 * h + 1]);
            }
        }
}

// ---------------- K4: assemble A_c (+ bf16 split) ----------------
__global__ void k_assemble() {
    int c = blockIdx.y;
    int t = blockIdx.x * 256 + threadIdx.x;
    int i = t >> 9, j = t & (D - 1);
    int tT = j * D + i;
    float g  = g_G[t] + g_T[t] + g_G0[t] + g_G0[tT];
    float g0 = g_NS0[t] + g_T[DD + t] + g_NS0[DD + t] + g_NS0[DD + tT];
    float gc = c ? (g - g0) : g0;
    float nc = g_cnt[c];
    float covc = (gc - nc * g_mean[c][i] * g_mean[c][j]) / (nc - 1.f);
    float task = (g - (float)NSUP * g_mall[i] * g_mall[j]) / ((float)NSUP - 1.f);
    float lam = fminf(nc / (nc + 1.f), 0.1f);
    float a = lam * covc + (1.f - lam) * task + ((i == j) ? 0.1f : 0.f);
    int idx = c * DD + t;
    g_A[idx] = a;
    __nv_bfloat16 h = __float2bfloat16(a);
    g_Ah[idx] = h;
    g_Al[idx] = __float2bfloat16(a - __bfloat162float(h));
}

// ---------------- K4b: Frobenius^2 of A^4 ----------------
__global__ void k_fro4(const float* __restrict__ M4) {
    int c = blockIdx.y;
    int t = blockIdx.x * 256 + threadIdx.x;
    float a = M4[(size_t)c * DD + t];
    __shared__ float red[256];
    red[threadIdx.x] = a * a;
    __syncthreads();
    for (int s = 128; s > 0; s >>= 1) {
        if (threadIdx.x < s) red[threadIdx.x] += red[threadIdx.x + s];
        __syncthreads();
    }
    if (threadIdx.x == 0) atomicAdd(&g_fro[c], red[0]);
}

// ---------------- K5: quadratic NS init X0 = u*I + v*A (+ split) ----------------
__global__ void k_init() {
    int c = blockIdx.y;
    int t = blockIdx.x * 256 + threadIdx.x;
    int i = t >> 9, j = t & (D - 1);
    float lub = 1.02f * powf(g_fro[c], 0.125f) + 0.02f;  // rigorous >= lambda_max
    float aa = 0.1f;
    float Ssum = aa * aa + 6.f * aa * lub + lub * lub;
    float u = 8.f * (aa + lub) / Ssum;
    float vv = -8.f / Ssum;
    int idx = c * DD + t;
    float v = vv * g_A[idx] + ((i == j) ? u : 0.f);
    g_NS0[idx] = v;
    __nv_bfloat16 h = __float2bfloat16(v);
    g_X0h[idx] = h;
    g_X0l[idx] = __float2bfloat16(v - __bfloat162float(h));
}

// ---------------- NS GEMM: C = A@B (mode0) or 2E - A@B (mode1), + bf16 split out ----------------
#define NSA 5120
#define NSB 4608
#define NS_BUF (NSA + NSB)
__global__ __launch_bounds__(256) void gemm_ns(
    const __nv_bfloat16* __restrict__ Ahp, const __nv_bfloat16* __restrict__ Alp,
    const __nv_bfloat16* __restrict__ Bhp, const __nv_bfloat16* __restrict__ Blp,
    const float* __restrict__ E, float* __restrict__ C,
    __nv_bfloat16* __restrict__ Ch, __nv_bfloat16* __restrict__ Cl,
    int mode, int nchunks) {
    __shared__ char sm[2 * NS_BUF];
    size_t zo = (size_t)blockIdx.z * DD;
    const char* Ah8 = (const char*)(Ahp + zo);
    const char* Al8 = (const char*)(Alp + zo);
    const char* Bh8 = (const char*)(Bhp + zo);
    const char* Bl8 = (const char*)(Blp + zo);
    E += zo; C += zo; Ch += zo; Cl += zo;
    uint32_t smb = smem_u32(sm);
    int tid = threadIdx.x, lane = tid & 31, wid = tid >> 5;
    int warp_m = (wid & 1) * 32, warp_n = (wid >> 1) * 16;
    int i0 = blockIdx.x * 64, j0 = blockIdx.y * 64;
    int ar = tid >> 2, aseg = (tid & 3) * 16;
    int br = tid >> 3, bseg = (tid & 7) * 16;

    float d[2][2][4];
#pragma unroll
    for (int a = 0; a < 2; a++)
#pragma unroll
        for (int b = 0; b < 2; b++)
#pragma unroll
            for (int k = 0; k < 4; k++) d[a][b][k] = 0.f;

    uint4 ra, rb;
#define NS_LOAD(c) do { \
        int p = (c) >> 4; int kb = ((c) & 15) * 64; \
        const char* Asrc = (p == 2) ? Al8 : Ah8; \
        const char* Bsrc = (p == 1) ? Bl8 : Bh8; \
        ra = *(const uint4*)(Asrc + (size_t)(i0 + ar) * 1024 + kb + aseg); \
        rb = *(const uint4*)(Bsrc + (size_t)(((c) & 15) * 32 + br) * 1024 + j0 * 2 + bseg); \
    } while (0)
#define NS_STS(buf) do { \
        *(uint4*)(sm + (buf) * NS_BUF + ar * 80 + aseg) = ra; \
        *(uint4*)(sm + (buf) * NS_BUF + NSA + br * 144 + bseg) = rb; \
    } while (0)

    NS_LOAD(0); NS_STS(0);
    __syncthreads();
    for (int c = 0; c < nchunks; c++) {
        int cur = c & 1;
        if (c < nchunks - 1) NS_LOAD(c + 1);
        uint32_t baseA = smb + cur * NS_BUF;
        uint32_t baseB = baseA + NSA;
#pragma unroll
        for (int ks = 0; ks < 2; ks++) {
            uint32_t afr[2][4], bfr[2][2], r4[4];
#pragma unroll
            for (int mi = 0; mi < 2; mi++)
                ldm4(afr[mi], baseA + (warp_m + mi * 16 + (lane & 15)) * 80 + (lane >> 4) * 16 + ks * 32);
            {
                int rowB = ks * 16 + ((lane >> 3) & 1) * 8 + (lane & 7);
                int colB = warp_n + (lane >> 4) * 8;
                ldm4t(r4, baseB + rowB * 144 + colB * 2);
            }
            bfr[0][0] = r4[0]; bfr[0][1] = r4[1]; bfr[1][0] = r4[2]; bfr[1][1] = r4[3];
#pragma unroll
            for (int mi = 0; mi < 2; mi++)
#pragma unroll
                for (int ni = 0; ni < 2; ni++)
                    mma16816(d[mi][ni], afr[mi], bfr[ni]);
        }
        if (c < nchunks - 1) NS_STS(1 - cur);
        __syncthreads();
    }
#pragma unroll
    for (int mi = 0; mi < 2; mi++)
#pragma unroll
        for (int ni = 0; ni < 2; ni++) {
            int col = j0 + warp_n + ni * 8 + 2 * (lane & 3);
#pragma unroll
            for (int h = 0; h < 2; h++) {
                int row = i0 + warp_m + mi * 16 + h * 8 + (lane >> 2);
                size_t idx = (size_t)row * D + col;
                float v0 = d[mi][ni][2 * h], v1 = d[mi][ni][2 * h + 1];
                if (mode) {
                    float2 e = *(const float2*)&E[idx];
                    v0 = 2.f * e.x - v0; v1 = 2.f * e.y - v1;
                }
                *(float2*)&C[idx] = make_float2(v0, v1);
                unsigned int hh, ll;
                bf16split2(v0, v1, hh, ll);
                *(unsigned int*)&Ch[idx] = hh;
                *(unsigned int*)&Cl[idx] = ll;
            }
        }
#undef NS_LOAD
#undef NS_STS
}

// ---------------- K6: w_c = P_c m_c (row-dots, P symmetric), b_c = m^T w ----------------
__global__ void k_wb(const float* __restrict__ P) {
    int c = blockIdx.x;
    int rg = blockIdx.y;
    __shared__ float smean[D];
    int tid = threadIdx.x, lane = tid & 31, wid = tid >> 5;
    for (int k = tid; k < D; k += 256) smean[k] = g_mean[c][k];
    __syncthreads();
    float bpart = 0.f;
    for (int rr = 0; rr < 8; rr++) {
        int r = rg * 64 + wid * 8 + rr;
        const float* row = P + (size_t)c * DD + (size_t)r * D;
        float s = 0.f;
        for (int k = lane; k < D; k += 32) s += row[k] * smean[k];
        for (int o = 16; o > 0; o >>= 1) s += __shfl_down_sync(0xffffffffu, s, o);
        if (lane == 0) { g_w[c][r] = s; bpart += s * smean[r]; }
    }
    if (lane == 0) atomicAdd(&g_b[c], bpart);
}

// ---------------- Q split fp32 -> bf16 hi only ----------------
__global__ void k_split(const float* __restrict__ S, __nv_bfloat16* __restrict__ H) {
    int i = blockIdx.x * 256 + threadIdx.x;
    float4 v = ((const float4*)S)[i];
    __nv_bfloat16 h0 = __float2bfloat16(v.x), h1 = __float2bfloat16(v.y);
    __nv_bfloat16 h2 = __float2bfloat16(v.z), h3 = __float2bfloat16(v.w);
    uint2 hh;
    hh.x = ((unsigned int)*(unsigned short*)&h0) | (((unsigned int)*(unsigned short*)&h1) << 16);
    hh.y = ((unsigned int)*(unsigned short*)&h2) | (((unsigned int)*(unsigned short*)&h3) << 16);
    ((uint2*)H)[i] = hh;
}

// ---------------- K7: main pass, 2-pass: H = Qh@(Ph+Pl); S = H . (2q - bf16(q)) ----------------
#define MB_BUF 20480
__global__ __launch_bounds__(256, 2) void k_main_mma(
    const float* __restrict__ Q,
    const __nv_bfloat16* __restrict__ Qh,
    const __nv_bfloat16* __restrict__ Phg, const __nv_bfloat16* __restrict__ Plg) {
    extern __shared__ char sm[];
    __shared__ float sRow[128][2];
    int cls = blockIdx.y;
    const char* Ph8 = (const char*)(Phg + (size_t)cls * DD);
    const char* Pl8 = (const char*)(Plg + (size_t)cls * DD);
    const char* Qh8 = (const char*)Qh;
    uint32_t smb = smem_u32(sm);
    int tid = threadIdx.x, lane = tid & 31, wid = tid >> 5;
    int warp_m = (wid >> 1) * 32, warp_n = (wid & 1) * 64;
    int q0 = blockIdx.x * 128;
    int r0 = tid >> 2, cseg = (tid & 3) * 16;
    float accS[4] = {0.f, 0.f, 0.f, 0.f};
    uint4 ra0, ra1, rb0, rb1;

#define MB_LOAD(c, n0) do { \
        int p = (c) >> 4; int kb = ((c) & 15) * 64 + cseg; \
        const char* Bsrc = p ? Pl8 : Ph8; \
        ra0 = *(const uint4*)(Qh8 + (size_t)(q0 + r0) * 1024 + kb); \
        ra1 = *(const uint4*)(Qh8 + (size_t)(q0 + 64 + r0) * 1024 + kb); \
        rb0 = *(const uint4*)(Bsrc + (size_t)((n0) + r0) * 1024 + kb); \
        rb1 = *(const uint4*)(Bsrc + (size_t)((n0) + 64 + r0) * 1024 + kb); \
    } while (0)
#define MB_STS(buf) do { \
        char* dA = sm + (buf) * MB_BUF + r0 * 80 + cseg; \
        *(uint4*)dA = ra0; *(uint4*)(dA + 64 * 80) = ra1; \
        char* dB = sm + (buf) * MB_BUF + 10240 + r0 * 80 + cseg; \
        *(uint4*)dB = rb0; *(uint4*)(dB + 64 * 80) = rb1; \
    } while (0)

    for (int nt = 0; nt < 4; nt++) {
        int n0 = nt * 128;
        float d[2][8][4];
#pragma unroll
        for (int a = 0; a < 2; a++)
#pragma unroll
            for (int b = 0; b < 8; b++)
#pragma unroll
                for (int k = 0; k < 4; k++) d[a][b][k] = 0.f;
        MB_LOAD(0, n0); MB_STS(0);
        __syncthreads();
        for (int c = 0; c < 32; c++) {
            int cur = c & 1;
            if (c < 31) MB_LOAD(c + 1, n0);
            uint32_t baseA = smb + cur * MB_BUF;
            uint32_t baseB = baseA + 10240;
#pragma unroll
            for (int ks = 0; ks < 2; ks++) {
                uint32_t afr[2][4], bfr[8][2], r4[4];
#pragma unroll
                for (int mi = 0; mi < 2; mi++)
                    ldm4(afr[mi], baseA + (warp_m + mi * 16 + (lane & 15)) * 80 + (lane >> 4) * 16 + ks * 32);
#pragma unroll
                for (int j = 0; j < 4; j++) {
                    ldm4(r4, baseB + (warp_n + j * 16 + ((lane >> 4) & 1) * 8 + (lane & 7)) * 80 + ((lane >> 3) & 1) * 16 + ks * 32);
                    bfr[2 * j][0] = r4[0]; bfr[2 * j][1] = r4[1];
                    bfr[2 * j + 1][0] = r4[2]; bfr[2 * j + 1][1] = r4[3];
                }
#pragma unroll
                for (int mi = 0; mi < 2; mi++)
#pragma unroll
                    for (int ni = 0; ni < 8; ni++)
                        mma16816(d[mi][ni], afr[mi], bfr[ni]);
            }
            if (c < 31) MB_STS(1 - cur);
            __syncthreads();
        }
#pragma unroll
        for (int mi = 0; mi < 2; mi++)
#pragma unroll
            for (int h = 0; h < 2; h++) {
                int row = q0 + warp_m + mi * 16 + h * 8 + (lane >> 2);
                float a = 0.f;
#pragma unroll
                for (int ni = 0; ni < 8; ni++) {
                    int col = n0 + warp_n + ni * 8 + 2 * (lane & 3);
                    float2 qv = *(const float2*)&Q[(size_t)row * D + col];
                    float v0 = 2.f * qv.x - __bfloat162float(__float2bfloat16(qv.x));
                    float v1 = 2.f * qv.y - __bfloat162float(__float2bfloat16(qv.y));
                    a += d[mi][ni][2 * h] * v0 + d[mi][ni][2 * h + 1] * v1;
                }
                accS[mi * 2 + h] += a;
            }
    }
#pragma unroll
    for (int i = 0; i < 4; i++) {
        accS[i] += __shfl_xor_sync(0xffffffffu, accS[i], 1);
        accS[i] += __shfl_xor_sync(0xffffffffu, accS[i], 2);
    }
    if ((lane & 3) == 0) {
#pragma unroll
        for (int mi = 0; mi < 2; mi++)
#pragma unroll
            for (int h = 0; h < 2; h++)
                sRow[warp_m + mi * 16 + h * 8 + (lane >> 2)][wid & 1] = accS[mi * 2 + h];
    }
    __syncthreads();
    if (tid < 128) g_S[cls][q0 + tid] = sRow[tid][0] + sRow[tid][1];
#undef MB_LOAD
#undef MB_STS
}

// ---------------- K8: logits ----------------
__global__ void k_final(const float* __restrict__ Q, float* __restrict__ out, int nq) {
    int w = (blockIdx.x * blockDim.x + threadIdx.x) >> 5;
    int lane = threadIdx.x & 31;
    if (w >= nq) return;
    float qw0 = 0.f, qw1 = 0.f;
    for (int k = lane; k < D; k += 32) {
        float qk = Q[w * D + k];
        qw0 += qk * g_w[0][k];
        qw1 += qk * g_w[1][k];
    }
    for (int o = 16; o > 0; o >>= 1) {
        qw0 += __shfl_down_sync(0xffffffffu, qw0, o);
        qw1 += __shfl_down_sync(0xffffffffu, qw1, o);
    }
    if (lane == 0) {
        out[w * 2 + 0] = -(g_S[0][w] - 2.f * qw0 + g_b[0]);
        out[w * 2 + 1] = -(g_S[1][w] - 2.f * qw1 + g_b[1]);
    }
}

// ---------------- launch ----------------
extern "C" void kernel_launch(void* const* d_in, const int* in_sizes, int n_in,
                              void* d_out, int out_size) {
    const float*        SF   = (const float*)d_in[0];
    const unsigned int* labw = (const unsigned int*)d_in[1];
    const float*        Q    = (const float*)d_in[2];
    float*              out  = (float*)d_out;
    int nq = in_sizes[2] / D;  // 16384

    float *pA, *pX0, *pX1, *pT, *pG, *pG0;
    __nv_bfloat16 *pQh, *pAh, *pAl, *pTh, *pTl, *pXh0, *pXl0, *pXh1, *pXl1;
    cudaGetSymbolAddress((void**)&pA, g_A);
    cudaGetSymbolAddress((void**)&pX0, g_NS0);
    cudaGetSymbolAddress((void**)&pX1, g_NS1);
    cudaGetSymbolAddress((void**)&pT, g_T);
    cudaGetSymbolAddress((void**)&pG, g_G);
    cudaGetSymbolAddress((void**)&pG0, g_G0);
    cudaGetSymbolAddress((void**)&pQh, g_Qh);
    cudaGetSymbolAddress((void**)&pAh, g_Ah);
    cudaGetSymbolAddress((void**)&pAl, g_Al);
    cudaGetSymbolAddress((void**)&pTh, g_Th);
    cudaGetSymbolAddress((void**)&pTl, g_Tl);
    cudaGetSymbolAddress((void**)&pXh0, g_X0h);
    cudaGetSymbolAddress((void**)&pXl0, g_X0l);
    cudaGetSymbolAddress((void**)&pXh1, g_X1h);
    cudaGetSymbolAddress((void**)&pXl1, g_X1l);
    cudaFuncSetAttribute(k_main_mma, cudaFuncAttributeMaxDynamicSharedMemorySize, 2 * MB_BUF);

    k_mask<<<1, NSUP>>>(labw);
    k_split2<<<DD / 1024, 256>>>(SF, pTh, pTl);  // support split (g_Th/g_Tl free until spectral)
    k_sums<<<dim3(4, 4), 128>>>(SF);
    k_means<<<2, D>>>();
    k_gram_tc<<<dim3(8, 8), 256>>>(pTh, pTl, pG, pG0, pT, pX0, pX0 + DD, pT + DD);
    k_assemble<<<dim3(DD / 256, 2), 256>>>();

    dim3 gns(8, 8, 2);
    // spectral bound: T = A@A (1-pass), NS1 = T@T, fro(NS1) -> lub = fro^(1/8)
    gemm_ns<<<gns, 256>>>(pAh, pAl, pAh, pAl, pT, pT, pTh, pTl, 0, 16);
    gemm_ns<<<gns, 256>>>(pTh, pTl, pTh, pTl, pT, pX1, pXh1, pXl1, 0, 16);
    k_fro4<<<dim3(DD / 256, 2), 256>>>(pX1);
    k_init<<<dim3(DD / 256, 2), 256>>>();

    float *X = pX0, *Xn = pX1;
    __nv_bfloat16 *Xh = pXh0, *Xl = pXl0, *Xnh = pXh1, *Xnl = pXl1;
    for (int it = 0; it < NIT_CHEAP + NIT_FULL; it++) {
        int nch = (it < NIT_CHEAP) ? 16 : 48;
        gemm_ns<<<gns, 256>>>(Xh, Xl, pAh, pAl, pT, pT, pTh, pTl, 0, nch);
        gemm_ns<<<gns, 256>>>(pTh, pTl, Xh, Xl, X, Xn, Xnh, Xnl, 1, nch);
        float* tf = X; X = Xn; Xn = tf;
        __nv_bfloat16* tb;
        tb = Xh; Xh = Xnh; Xnh = tb;
        tb = Xl; Xl = Xnl; Xnl = tb;
    }

    k_wb<<<dim3(2, 8), 256>>>(X);
    k_split<<<(nq * D) / 1024, 256>>>(Q, pQh);
    k_main_mma<<<dim3(nq / 128, 2), 256, 2 * MB_BUF>>>(Q, pQh, Xh, Xl);
    k_final<<<(nq * 32 + 255) / 256, 256>>>(Q, out, nq);
}